// round 1
// baseline (speedup 1.0000x reference)
#include <cuda_runtime.h>
#include <cuda_bf16.h>
#include <math.h>

#define MTOK   73728
#define CDIM   192
#define NHEAD  6
#define HD     32
#define NTOK   144
#define NWIN   512
#define TWIN   32
#define NWW    16
#define NB     3312
#define QKVN   576
#define FFN    768

__device__ float g_x  [(size_t)MTOK * CDIM];
__device__ float g_xw [(size_t)MTOK * CDIM];
__device__ float g_qkv[(size_t)MTOK * QKVN];
__device__ float g_ao [(size_t)MTOK * CDIM];
__device__ float g_tmp[(size_t)MTOK * CDIM];
__device__ float g_h  [(size_t)MTOK * FFN];
__device__ float g_bm [(size_t)2 * TWIN * NHEAD * NTOK * NTOK];

// Dense (relative-position bias + shift mask):
// g_bm[L][t][head][n][m] = bias_table[L][pos(n,m)][t][head] + (L==1 ? mask : 0)
__global__ void biasmask_kernel(const float* __restrict__ table) {
    size_t idx = (size_t)blockIdx.x * blockDim.x + threadIdx.x;
    size_t total = (size_t)2 * TWIN * NHEAD * NTOK * NTOK;
    if (idx >= total) return;
    int m = idx % NTOK; size_t r = idx / NTOK;
    int n = r % NTOK;   r /= NTOK;
    int head = r % NHEAD; r /= NHEAD;
    int t = r % TWIN;   int L = (int)(r / TWIN);
    int z1 = n / 72, h1 = (n % 72) / 12, w1 = n % 12;
    int z2 = m / 72, h2 = (m % 72) / 12, w2 = m % 12;
    int pos = 828 * (z1 + 2 * z2) + 23 * (h1 + 6 * h2) + (w1 - w2 + 11);
    float v = table[(((size_t)L * NB + pos) * TWIN + t) * NHEAD + head];
    if (L == 1) {
        int tz = t / 8, th = t % 8;
        int idn = (((tz * 2 + z1) >= 1) ? 2 : 0) + (((th * 6 + h1) >= 3) ? 1 : 0);
        int idm = (((tz * 2 + z2) >= 1) ? 2 : 0) + (((th * 6 + h2) >= 3) ? 1 : 0);
        if (idn != idm) v += -10000.0f;
    }
    g_bm[idx] = v;
}

// Window gather: xw[r][:] = x[src(r)][:]
__global__ void gather_kernel(int rolled) {
    int idx = blockIdx.x * blockDim.x + threadIdx.x;
    if (idx >= MTOK * 48) return;
    int c4 = idx % 48;
    int r  = idx / 48;
    int n   = r % NTOK;
    int win = r / NTOK;
    int l = win % NWW, t = win / NWW;
    int tz = t / 8, th = t % 8;
    int z1 = n / 72, h1 = (n % 72) / 12, w1 = n % 12;
    int zr = tz * 2 + z1, hr = th * 6 + h1, wr = l * 12 + w1;
    int z, hh, ww;
    if (rolled) { z = (zr + 7) & 7; hh = (hr + 45) % 48; ww = (wr + 186) % 192; }
    else        { z = zr; hh = hr; ww = wr; }
    size_t p = ((size_t)z * 48 + hh) * 192 + ww;
    reinterpret_cast<float4*>(g_xw)[(size_t)r * 48 + c4] =
        reinterpret_cast<const float4*>(g_x)[p * 48 + c4];
}

__device__ __forceinline__ float gelu_exact(float v) {
    return 0.5f * v * (1.0f + erff(v * 0.70710678118654752f));
}

// SGEMM: C = A(MxK,rm)*B(KxN,rm)+bias [,GELU]; 64x64x16 tile, 256 thr, 4x4.
template <int EPI>
__global__ void sgemm_kernel(const float* __restrict__ A,
                             const float* __restrict__ B,
                             const float* __restrict__ bias,
                             float* __restrict__ Cm,
                             int K, int Nn) {
    __shared__ float As[16][68];
    __shared__ float Bs[16][64];
    int tx = threadIdx.x & 15, ty = threadIdx.x >> 4;
    int m0 = blockIdx.y * 64, n0 = blockIdx.x * 64;

    int ar = threadIdx.x >> 2;
    int ak = (threadIdx.x & 3) * 4;
    int bk = threadIdx.x >> 4;
    int bn = (threadIdx.x & 15) * 4;

    const float* Ap = A + (size_t)(m0 + ar) * K + ak;
    const float* Bp = B + (size_t)bk * Nn + n0 + bn;

    float c[4][4] = {};
    for (int k0 = 0; k0 < K; k0 += 16) {
        float4 a4 = *reinterpret_cast<const float4*>(Ap + k0);
        As[ak + 0][ar] = a4.x; As[ak + 1][ar] = a4.y;
        As[ak + 2][ar] = a4.z; As[ak + 3][ar] = a4.w;
        *reinterpret_cast<float4*>(&Bs[bk][bn]) =
            *reinterpret_cast<const float4*>(Bp + (size_t)k0 * Nn);
        __syncthreads();
        #pragma unroll
        for (int k = 0; k < 16; k++) {
            float4 av = *reinterpret_cast<const float4*>(&As[k][ty * 4]);
            float4 bv = *reinterpret_cast<const float4*>(&Bs[k][tx * 4]);
            float aa[4] = {av.x, av.y, av.z, av.w};
            float bb[4] = {bv.x, bv.y, bv.z, bv.w};
            #pragma unroll
            for (int i = 0; i < 4; i++)
                #pragma unroll
                for (int j = 0; j < 4; j++)
                    c[i][j] = fmaf(aa[i], bb[j], c[i][j]);
        }
        __syncthreads();
    }
    float4 bb4 = *reinterpret_cast<const float4*>(bias + n0 + tx * 4);
    float bv[4] = {bb4.x, bb4.y, bb4.z, bb4.w};
    #pragma unroll
    for (int i = 0; i < 4; i++) {
        int m = m0 + ty * 4 + i;
        float o[4];
        #pragma unroll
        for (int j = 0; j < 4; j++) {
            float v = c[i][j] + bv[j];
            o[j] = (EPI == 1) ? gelu_exact(v) : v;
        }
        *reinterpret_cast<float4*>(Cm + (size_t)m * Nn + n0 + tx * 4) =
            make_float4(o[0], o[1], o[2], o[3]);
    }
}

// Window attention: block = (window, head); q/k/v + scores in dynamic smem.
__global__ void attn_kernel(int L) {
    int win  = blockIdx.x;
    int head = blockIdx.y;
    int t = win >> 4;
    extern __shared__ float sm[];
    float* qs = sm;
    float* ks = qs + NTOK * HD;
    float* vs = ks + NTOK * HD;
    float* s  = vs + NTOK * HD;   // rows of stride 145 (bank-conflict-free)

    int tid = threadIdx.x;
    const float* base = g_qkv + (size_t)win * NTOK * QKVN;
    int hc4 = head * 8;
    for (int idx = tid; idx < NTOK * 8; idx += blockDim.x) {
        int row = idx >> 3, j = idx & 7;
        const float4* rp = reinterpret_cast<const float4*>(base + (size_t)row * QKVN);
        reinterpret_cast<float4*>(qs)[row * 8 + j] = rp[hc4 + j];
        reinterpret_cast<float4*>(ks)[row * 8 + j] = rp[48 + hc4 + j];
        reinterpret_cast<float4*>(vs)[row * 8 + j] = rp[96 + hc4 + j];
    }
    __syncthreads();

    if (tid < NTOK) {
        const int n = tid;
        float q[HD];
        #pragma unroll
        for (int d = 0; d < HD; d++)
            q[d] = qs[n * HD + d] * 0.17677669529663687f;   // 1/sqrt(32)

        const float* bmn = g_bm + ((((size_t)L * TWIN + t) * NHEAD + head) * NTOK + n) * NTOK;
        float* srow = s + n * 145;

        for (int m = 0; m < NTOK; m++) {
            float acc = bmn[m];
            const float4* kv = reinterpret_cast<const float4*>(ks + m * HD);
            #pragma unroll
            for (int j = 0; j < 8; j++) {
                float4 k4 = kv[j];
                acc = fmaf(q[4*j+0], k4.x, acc);
                acc = fmaf(q[4*j+1], k4.y, acc);
                acc = fmaf(q[4*j+2], k4.z, acc);
                acc = fmaf(q[4*j+3], k4.w, acc);
            }
            srow[m] = acc;
        }
        float mx = -1e30f;
        for (int m = 0; m < NTOK; m++) mx = fmaxf(mx, srow[m]);
        float sum = 0.0f;
        for (int m = 0; m < NTOK; m++) {
            float e = expf(srow[m] - mx);
            srow[m] = e;
            sum += e;
        }
        float inv = 1.0f / sum;

        float o[HD];
        #pragma unroll
        for (int d = 0; d < HD; d++) o[d] = 0.0f;
        for (int m = 0; m < NTOK; m++) {
            float p = srow[m];
            const float4* vv = reinterpret_cast<const float4*>(vs + m * HD);
            #pragma unroll
            for (int j = 0; j < 8; j++) {
                float4 v4 = vv[j];
                o[4*j+0] = fmaf(p, v4.x, o[4*j+0]);
                o[4*j+1] = fmaf(p, v4.y, o[4*j+1]);
                o[4*j+2] = fmaf(p, v4.z, o[4*j+2]);
                o[4*j+3] = fmaf(p, v4.w, o[4*j+3]);
            }
        }
        float* op = g_ao + ((size_t)win * NTOK + n) * CDIM + head * HD;
        #pragma unroll
        for (int j = 0; j < 8; j++)
            reinterpret_cast<float4*>(op)[j] =
                make_float4(o[4*j]*inv, o[4*j+1]*inv, o[4*j+2]*inv, o[4*j+3]*inv);
    }
}

// LayerNorm + residual: x[p] += LN(y[r])*g + b. mode 0: p=r; 1: un-window;
// 2: un-window + un-roll. One warp per row (192 ch = 6/lane).
__global__ void ln_add_kernel(const float* __restrict__ y,
                              const float* __restrict__ g,
                              const float* __restrict__ b,
                              int mode) {
    int w = (blockIdx.x * blockDim.x + threadIdx.x) >> 5;
    int lane = threadIdx.x & 31;
    if (w >= MTOK) return;
    size_t p;
    if (mode == 0) {
        p = (size_t)w;
    } else {
        int n = w % NTOK, win = w / NTOK;
        int l = win % NWW, t = win / NWW;
        int tz = t / 8, th = t % 8;
        int z1 = n / 72, h1 = (n % 72) / 12, w1 = n % 12;
        int zr = tz * 2 + z1, hr = th * 6 + h1, wr = l * 12 + w1;
        int z, hh, ww;
        if (mode == 2) { z = (zr + 7) & 7; hh = (hr + 45) % 48; ww = (wr + 186) % 192; }
        else           { z = zr; hh = hr; ww = wr; }
        p = ((size_t)z * 48 + hh) * 192 + ww;
    }
    const float* yr = y + (size_t)w * CDIM;
    float v[6];
    float sum = 0.0f;
    #pragma unroll
    for (int i = 0; i < 6; i++) { v[i] = yr[lane + 32 * i]; sum += v[i]; }
    #pragma unroll
    for (int o = 16; o; o >>= 1) sum += __shfl_xor_sync(0xFFFFFFFFu, sum, o);
    float mu = sum * (1.0f / 192.0f);
    float var = 0.0f;
    #pragma unroll
    for (int i = 0; i < 6; i++) { float d = v[i] - mu; var += d * d; }
    #pragma unroll
    for (int o = 16; o; o >>= 1) var += __shfl_xor_sync(0xFFFFFFFFu, var, o);
    var *= (1.0f / 192.0f);
    float rs = rsqrtf(var + 1e-5f);
    float* xp = g_x + p * CDIM;
    #pragma unroll
    for (int i = 0; i < 6; i++) {
        int c = lane + 32 * i;
        xp[c] += (v[i] - mu) * rs * g[c] + b[c];
    }
}

extern "C" void kernel_launch(void* const* d_in, const int* in_sizes, int n_in,
                              void* d_out, int out_size) {
    const float* x_in       = (const float*)d_in[0];
    const float* qkv_w      = (const float*)d_in[1];
    const float* qkv_b      = (const float*)d_in[2];
    const float* proj_w     = (const float*)d_in[3];
    const float* proj_b     = (const float*)d_in[4];
    const float* bias_table = (const float*)d_in[5];
    const float* n1_g       = (const float*)d_in[6];
    const float* n1_b       = (const float*)d_in[7];
    const float* n2_g       = (const float*)d_in[8];
    const float* n2_b       = (const float*)d_in[9];
    const float* w1         = (const float*)d_in[10];
    const float* b1         = (const float*)d_in[11];
    const float* w2         = (const float*)d_in[12];
    const float* b2         = (const float*)d_in[13];
    // d_in[14..16] = Z,H,W scalars (fixed 8,48,192 for this problem)

    float *gx, *gxw, *gqkv, *gao, *gtmp, *gh;
    cudaGetSymbolAddress((void**)&gx,   g_x);
    cudaGetSymbolAddress((void**)&gxw,  g_xw);
    cudaGetSymbolAddress((void**)&gqkv, g_qkv);
    cudaGetSymbolAddress((void**)&gao,  g_ao);
    cudaGetSymbolAddress((void**)&gtmp, g_tmp);
    cudaGetSymbolAddress((void**)&gh,   g_h);

    const size_t xbytes = (size_t)MTOK * CDIM * sizeof(float);
    cudaMemcpyAsync(gx, x_in, xbytes, cudaMemcpyDeviceToDevice);

    {
        size_t total = (size_t)2 * TWIN * NHEAD * NTOK * NTOK;
        biasmask_kernel<<<(unsigned)((total + 255) / 256), 256>>>(bias_table);
    }

    const int ATTN_SMEM = (3 * NTOK * HD + NTOK * 145) * (int)sizeof(float);  // 138816 B
    cudaFuncSetAttribute(attn_kernel, cudaFuncAttributeMaxDynamicSharedMemorySize, ATTN_SMEM);

    for (int L = 0; L < 2; L++) {
        gather_kernel<<<(MTOK * 48 + 255) / 256, 256>>>(L);

        // QKV: (M x 192) @ (192 x 576) + b
        sgemm_kernel<0><<<dim3(QKVN / 64, MTOK / 64), 256>>>(
            gxw, qkv_w + (size_t)L * CDIM * QKVN, qkv_b + (size_t)L * QKVN,
            gqkv, CDIM, QKVN);

        attn_kernel<<<dim3(NWIN, NHEAD), 160, ATTN_SMEM>>>(L);

        // proj: (M x 192) @ (192 x 192) + b
        sgemm_kernel<0><<<dim3(CDIM / 64, MTOK / 64), 256>>>(
            gao, proj_w + (size_t)L * CDIM * CDIM, proj_b + (size_t)L * CDIM,
            gtmp, CDIM, CDIM);

        // x += LN(un-window(proj_out))
        ln_add_kernel<<<(MTOK * 32 + 255) / 256, 256>>>(
            gtmp, n1_g + (size_t)L * CDIM, n1_b + (size_t)L * CDIM, L ? 2 : 1);

        // MLP up: gelu((M x 192) @ (192 x 768) + b)
        sgemm_kernel<1><<<dim3(FFN / 64, MTOK / 64), 256>>>(
            gx, w1 + (size_t)L * CDIM * FFN, b1 + (size_t)L * FFN,
            gh, CDIM, FFN);

        // MLP down: (M x 768) @ (768 x 192) + b
        sgemm_kernel<0><<<dim3(CDIM / 64, MTOK / 64), 256>>>(
            gh, w2 + (size_t)L * FFN * CDIM, b2 + (size_t)L * CDIM,
            gtmp, FFN, CDIM);

        // x += LN(mlp_out)
        ln_add_kernel<<<(MTOK * 32 + 255) / 256, 256>>>(
            gtmp, n2_g + (size_t)L * CDIM, n2_b + (size_t)L * CDIM, 0);
    }

    cudaMemcpyAsync(d_out, gx, xbytes, cudaMemcpyDeviceToDevice);
}

// round 2
// speedup vs baseline: 1.8058x; 1.8058x over previous
#include <cuda_runtime.h>
#include <cuda_bf16.h>
#include <math.h>

#define MTOK   73728
#define CDIM   192
#define NHEAD  6
#define HD     32
#define NTOK   144
#define NWIN   512
#define TWIN   32
#define NWW    16
#define NB     3312
#define QKVN   576
#define FFN    768

__device__ float g_x  [(size_t)MTOK * CDIM];
__device__ float g_xw [(size_t)MTOK * CDIM];
__device__ float g_qkv[(size_t)MTOK * QKVN];
__device__ float g_ao [(size_t)MTOK * CDIM];
__device__ float g_tmp[(size_t)MTOK * CDIM];
__device__ float g_h  [(size_t)MTOK * FFN];
__device__ float g_bm [(size_t)2 * TWIN * NHEAD * NTOK * NTOK];

// ---------------------------------------------------------------------------
// Dense (relative-position bias + shift mask):
// g_bm[L][t][head][n][m] = bias_table[L][pos(n,m)][t][head] + (L==1 ? mask : 0)
// ---------------------------------------------------------------------------
__global__ void biasmask_kernel(const float* __restrict__ table) {
    size_t idx = (size_t)blockIdx.x * blockDim.x + threadIdx.x;
    size_t total = (size_t)2 * TWIN * NHEAD * NTOK * NTOK;
    if (idx >= total) return;
    int m = idx % NTOK; size_t r = idx / NTOK;
    int n = r % NTOK;   r /= NTOK;
    int head = r % NHEAD; r /= NHEAD;
    int t = r % TWIN;   int L = (int)(r / TWIN);
    int z1 = n / 72, h1 = (n % 72) / 12, w1 = n % 12;
    int z2 = m / 72, h2 = (m % 72) / 12, w2 = m % 12;
    int pos = 828 * (z1 + 2 * z2) + 23 * (h1 + 6 * h2) + (w1 - w2 + 11);
    float v = table[(((size_t)L * NB + pos) * TWIN + t) * NHEAD + head];
    if (L == 1) {
        int tz = t / 8, th = t % 8;
        int idn = (((tz * 2 + z1) >= 1) ? 2 : 0) + (((th * 6 + h1) >= 3) ? 1 : 0);
        int idm = (((tz * 2 + z2) >= 1) ? 2 : 0) + (((th * 6 + h2) >= 3) ? 1 : 0);
        if (idn != idm) v += -10000.0f;
    }
    g_bm[idx] = v;
}

// Window gather: xw[r][:] = x[src(r)][:]
__global__ void gather_kernel(int rolled) {
    int idx = blockIdx.x * blockDim.x + threadIdx.x;
    if (idx >= MTOK * 48) return;
    int c4 = idx % 48;
    int r  = idx / 48;
    int n   = r % NTOK;
    int win = r / NTOK;
    int l = win % NWW, t = win / NWW;
    int tz = t / 8, th = t % 8;
    int z1 = n / 72, h1 = (n % 72) / 12, w1 = n % 12;
    int zr = tz * 2 + z1, hr = th * 6 + h1, wr = l * 12 + w1;
    int z, hh, ww;
    if (rolled) { z = (zr + 7) & 7; hh = (hr + 45) % 48; ww = (wr + 186) % 192; }
    else        { z = zr; hh = hr; ww = wr; }
    size_t p = ((size_t)z * 48 + hh) * 192 + ww;
    reinterpret_cast<float4*>(g_xw)[(size_t)r * 48 + c4] =
        reinterpret_cast<const float4*>(g_x)[p * 48 + c4];
}

__device__ __forceinline__ float gelu_exact(float v) {
    return 0.5f * v * (1.0f + erff(v * 0.70710678118654752f));
}

// ---------------------------------------------------------------------------
// tf32 tensor-core GEMM: C = A(MxK,rm) * B(KxN,rm) + bias [, GELU]
// Tile BM=128, BN=64, BK=16; 256 threads; warps 4(m) x 2(n); warp tile 32x32.
// mma.sync.aligned.m16n8k8.row.col.f32.tf32.tf32.f32, fp32 accumulate.
// M % 128 == 0, N % 64 == 0, K % 16 == 0 hold for all four GEMMs here.
// ---------------------------------------------------------------------------
__device__ __forceinline__ unsigned f2tf32(float x) {
    unsigned r;
    asm("cvt.rna.tf32.f32 %0, %1;" : "=r"(r) : "f"(x));
    return r;
}

__device__ __forceinline__ void mma_tf32(float* d, const unsigned* a, const unsigned* b) {
    asm volatile(
        "mma.sync.aligned.m16n8k8.row.col.f32.tf32.tf32.f32 "
        "{%0,%1,%2,%3}, {%4,%5,%6,%7}, {%8,%9}, {%0,%1,%2,%3};\n"
        : "+f"(d[0]), "+f"(d[1]), "+f"(d[2]), "+f"(d[3])
        : "r"(a[0]), "r"(a[1]), "r"(a[2]), "r"(a[3]),
          "r"(b[0]), "r"(b[1]));
}

template <int EPI>
__global__ void __launch_bounds__(256)
mma_gemm_kernel(const float* __restrict__ A,
                const float* __restrict__ B,
                const float* __restrict__ bias,
                float* __restrict__ Cm,
                int K, int Nn) {
    __shared__ unsigned As[128 * 20];   // [row][k] stride 20 (pad 4)
    __shared__ unsigned Bs[16 * 68];    // [k][n]  stride 68 (pad 4)

    const int tid  = threadIdx.x;
    const int lane = tid & 31;
    const int wid  = tid >> 5;
    const int wm   = wid >> 1;          // 0..3
    const int wn   = wid & 1;           // 0..1
    const int g    = lane >> 2;         // groupID 0..7
    const int tg   = lane & 3;          // threadID_in_group 0..3
    const int m0   = blockIdx.y * 128;
    const int n0   = blockIdx.x * 64;

    float acc[2][4][4];
    #pragma unroll
    for (int mt = 0; mt < 2; mt++)
        #pragma unroll
        for (int nt = 0; nt < 4; nt++)
            #pragma unroll
            for (int i = 0; i < 4; i++) acc[mt][nt][i] = 0.0f;

    for (int k0 = 0; k0 < K; k0 += 16) {
        // A tile: 128x16 = 512 float4; 2 per thread
        #pragma unroll
        for (int i = 0; i < 2; i++) {
            int id  = tid + i * 256;
            int row = id >> 2, c4 = id & 3;
            const float4 v = *reinterpret_cast<const float4*>(
                A + (size_t)(m0 + row) * K + k0 + c4 * 4);
            unsigned* dst = &As[row * 20 + c4 * 4];
            dst[0] = f2tf32(v.x); dst[1] = f2tf32(v.y);
            dst[2] = f2tf32(v.z); dst[3] = f2tf32(v.w);
        }
        // B tile: 16x64 = 256 float4; 1 per thread
        {
            int row = tid >> 4, c4 = tid & 15;
            const float4 v = *reinterpret_cast<const float4*>(
                B + (size_t)(k0 + row) * Nn + n0 + c4 * 4);
            unsigned* dst = &Bs[row * 68 + c4 * 4];
            dst[0] = f2tf32(v.x); dst[1] = f2tf32(v.y);
            dst[2] = f2tf32(v.z); dst[3] = f2tf32(v.w);
        }
        __syncthreads();

        #pragma unroll
        for (int ks = 0; ks < 2; ks++) {
            const int kk = ks * 8;
            unsigned af[2][4], bf[4][2];
            #pragma unroll
            for (int mt = 0; mt < 2; mt++) {
                int rb = wm * 32 + mt * 16;
                af[mt][0] = As[(rb + g)     * 20 + kk + tg];
                af[mt][1] = As[(rb + 8 + g) * 20 + kk + tg];
                af[mt][2] = As[(rb + g)     * 20 + kk + tg + 4];
                af[mt][3] = As[(rb + 8 + g) * 20 + kk + tg + 4];
            }
            #pragma unroll
            for (int nt = 0; nt < 4; nt++) {
                int cb = wn * 32 + nt * 8;
                bf[nt][0] = Bs[(kk + tg)     * 68 + cb + g];
                bf[nt][1] = Bs[(kk + 4 + tg) * 68 + cb + g];
            }
            #pragma unroll
            for (int mt = 0; mt < 2; mt++)
                #pragma unroll
                for (int nt = 0; nt < 4; nt++)
                    mma_tf32(acc[mt][nt], af[mt], bf[nt]);
        }
        __syncthreads();
    }

    // Epilogue: +bias [, GELU], float2 stores
    #pragma unroll
    for (int mt = 0; mt < 2; mt++) {
        int r0 = m0 + wm * 32 + mt * 16 + g;
        #pragma unroll
        for (int nt = 0; nt < 4; nt++) {
            int c = n0 + wn * 32 + nt * 8 + tg * 2;
            float b0 = bias[c], b1 = bias[c + 1];
            float v0 = acc[mt][nt][0] + b0;
            float v1 = acc[mt][nt][1] + b1;
            float v2 = acc[mt][nt][2] + b0;
            float v3 = acc[mt][nt][3] + b1;
            if (EPI == 1) {
                v0 = gelu_exact(v0); v1 = gelu_exact(v1);
                v2 = gelu_exact(v2); v3 = gelu_exact(v3);
            }
            *reinterpret_cast<float2*>(Cm + (size_t)r0 * Nn + c)       = make_float2(v0, v1);
            *reinterpret_cast<float2*>(Cm + (size_t)(r0 + 8) * Nn + c) = make_float2(v2, v3);
        }
    }
}

// ---------------------------------------------------------------------------
// Window attention, flash-style (online softmax, no score buffer).
// block = (window, head); q/k/v in 55 KB dynamic smem -> 4 blocks/SM.
// ---------------------------------------------------------------------------
__global__ void __launch_bounds__(160, 4) attn_kernel(int L) {
    int win  = blockIdx.x;
    int head = blockIdx.y;
    int t = win >> 4;
    extern __shared__ float sm[];
    float* qs = sm;
    float* ks = qs + NTOK * HD;
    float* vs = ks + NTOK * HD;

    int tid = threadIdx.x;
    const float* base = g_qkv + (size_t)win * NTOK * QKVN;
    int hc4 = head * 8;
    for (int idx = tid; idx < NTOK * 8; idx += blockDim.x) {
        int row = idx >> 3, j = idx & 7;
        const float4* rp = reinterpret_cast<const float4*>(base + (size_t)row * QKVN);
        reinterpret_cast<float4*>(qs)[row * 8 + j] = rp[hc4 + j];
        reinterpret_cast<float4*>(ks)[row * 8 + j] = rp[48 + hc4 + j];
        reinterpret_cast<float4*>(vs)[row * 8 + j] = rp[96 + hc4 + j];
    }
    __syncthreads();

    if (tid < NTOK) {
        const int n = tid;
        float q[HD];
        #pragma unroll
        for (int d = 0; d < HD; d++)
            q[d] = qs[n * HD + d] * 0.17677669529663687f;   // 1/sqrt(32)

        const float* bmn = g_bm + ((((size_t)L * TWIN + t) * NHEAD + head) * NTOK + n) * NTOK;

        float mx = -1e30f, sum = 0.0f;
        float o[HD];
        #pragma unroll
        for (int d = 0; d < HD; d++) o[d] = 0.0f;

        for (int m = 0; m < NTOK; m++) {
            float acc = bmn[m];
            const float4* kv = reinterpret_cast<const float4*>(ks + m * HD);
            #pragma unroll
            for (int j = 0; j < 8; j++) {
                float4 k4 = kv[j];
                acc = fmaf(q[4*j+0], k4.x, acc);
                acc = fmaf(q[4*j+1], k4.y, acc);
                acc = fmaf(q[4*j+2], k4.z, acc);
                acc = fmaf(q[4*j+3], k4.w, acc);
            }
            float nmx  = fmaxf(mx, acc);
            float corr = __expf(mx - nmx);     // 1.0 when max unchanged
            float e    = __expf(acc - nmx);
            sum = sum * corr + e;
            mx  = nmx;
            const float4* vv = reinterpret_cast<const float4*>(vs + m * HD);
            #pragma unroll
            for (int j = 0; j < 8; j++) {
                float4 v4 = vv[j];
                o[4*j+0] = fmaf(e, v4.x, o[4*j+0] * corr);
                o[4*j+1] = fmaf(e, v4.y, o[4*j+1] * corr);
                o[4*j+2] = fmaf(e, v4.z, o[4*j+2] * corr);
                o[4*j+3] = fmaf(e, v4.w, o[4*j+3] * corr);
            }
        }
        float inv = 1.0f / sum;
        float* op = g_ao + ((size_t)win * NTOK + n) * CDIM + head * HD;
        #pragma unroll
        for (int j = 0; j < 8; j++)
            reinterpret_cast<float4*>(op)[j] =
                make_float4(o[4*j]*inv, o[4*j+1]*inv, o[4*j+2]*inv, o[4*j+3]*inv);
    }
}

// ---------------------------------------------------------------------------
// LayerNorm + residual: x[p] += LN(y[r])*g + b. mode 0: p=r; 1: un-window;
// 2: un-window + un-roll. One warp per row.
// ---------------------------------------------------------------------------
__global__ void ln_add_kernel(const float* __restrict__ y,
                              const float* __restrict__ g,
                              const float* __restrict__ b,
                              int mode) {
    int w = (blockIdx.x * blockDim.x + threadIdx.x) >> 5;
    int lane = threadIdx.x & 31;
    if (w >= MTOK) return;
    size_t p;
    if (mode == 0) {
        p = (size_t)w;
    } else {
        int n = w % NTOK, win = w / NTOK;
        int l = win % NWW, t = win / NWW;
        int tz = t / 8, th = t % 8;
        int z1 = n / 72, h1 = (n % 72) / 12, w1 = n % 12;
        int zr = tz * 2 + z1, hr = th * 6 + h1, wr = l * 12 + w1;
        int z, hh, ww;
        if (mode == 2) { z = (zr + 7) & 7; hh = (hr + 45) % 48; ww = (wr + 186) % 192; }
        else           { z = zr; hh = hr; ww = wr; }
        p = ((size_t)z * 48 + hh) * 192 + ww;
    }
    const float* yr = y + (size_t)w * CDIM;
    float v[6];
    float sum = 0.0f;
    #pragma unroll
    for (int i = 0; i < 6; i++) { v[i] = yr[lane + 32 * i]; sum += v[i]; }
    #pragma unroll
    for (int o = 16; o; o >>= 1) sum += __shfl_xor_sync(0xFFFFFFFFu, sum, o);
    float mu = sum * (1.0f / 192.0f);
    float var = 0.0f;
    #pragma unroll
    for (int i = 0; i < 6; i++) { float d = v[i] - mu; var += d * d; }
    #pragma unroll
    for (int o = 16; o; o >>= 1) var += __shfl_xor_sync(0xFFFFFFFFu, var, o);
    var *= (1.0f / 192.0f);
    float rs = rsqrtf(var + 1e-5f);
    float* xp = g_x + p * CDIM;
    #pragma unroll
    for (int i = 0; i < 6; i++) {
        int c = lane + 32 * i;
        xp[c] += (v[i] - mu) * rs * g[c] + b[c];
    }
}

extern "C" void kernel_launch(void* const* d_in, const int* in_sizes, int n_in,
                              void* d_out, int out_size) {
    const float* x_in       = (const float*)d_in[0];
    const float* qkv_w      = (const float*)d_in[1];
    const float* qkv_b      = (const float*)d_in[2];
    const float* proj_w     = (const float*)d_in[3];
    const float* proj_b     = (const float*)d_in[4];
    const float* bias_table = (const float*)d_in[5];
    const float* n1_g       = (const float*)d_in[6];
    const float* n1_b       = (const float*)d_in[7];
    const float* n2_g       = (const float*)d_in[8];
    const float* n2_b       = (const float*)d_in[9];
    const float* w1         = (const float*)d_in[10];
    const float* b1         = (const float*)d_in[11];
    const float* w2         = (const float*)d_in[12];
    const float* b2         = (const float*)d_in[13];
    // d_in[14..16] = Z,H,W scalars (fixed 8,48,192 for this problem)

    float *gx, *gxw, *gqkv, *gao, *gtmp, *gh;
    cudaGetSymbolAddress((void**)&gx,   g_x);
    cudaGetSymbolAddress((void**)&gxw,  g_xw);
    cudaGetSymbolAddress((void**)&gqkv, g_qkv);
    cudaGetSymbolAddress((void**)&gao,  g_ao);
    cudaGetSymbolAddress((void**)&gtmp, g_tmp);
    cudaGetSymbolAddress((void**)&gh,   g_h);

    const size_t xbytes = (size_t)MTOK * CDIM * sizeof(float);
    cudaMemcpyAsync(gx, x_in, xbytes, cudaMemcpyDeviceToDevice);

    {
        size_t total = (size_t)2 * TWIN * NHEAD * NTOK * NTOK;
        biasmask_kernel<<<(unsigned)((total + 255) / 256), 256>>>(bias_table);
    }

    const int ATTN_SMEM = 3 * NTOK * HD * (int)sizeof(float);   // 55296 B
    cudaFuncSetAttribute(attn_kernel, cudaFuncAttributeMaxDynamicSharedMemorySize, ATTN_SMEM);

    for (int L = 0; L < 2; L++) {
        gather_kernel<<<(MTOK * 48 + 255) / 256, 256>>>(L);

        // QKV: (M x 192) @ (192 x 576) + b
        mma_gemm_kernel<0><<<dim3(QKVN / 64, MTOK / 128), 256>>>(
            gxw, qkv_w + (size_t)L * CDIM * QKVN, qkv_b + (size_t)L * QKVN,
            gqkv, CDIM, QKVN);

        attn_kernel<<<dim3(NWIN, NHEAD), 160, ATTN_SMEM>>>(L);

        // proj: (M x 192) @ (192 x 192) + b
        mma_gemm_kernel<0><<<dim3(CDIM / 64, MTOK / 128), 256>>>(
            gao, proj_w + (size_t)L * CDIM * CDIM, proj_b + (size_t)L * CDIM,
            gtmp, CDIM, CDIM);

        // x += LN(un-window(proj_out))
        ln_add_kernel<<<(MTOK * 32 + 255) / 256, 256>>>(
            gtmp, n1_g + (size_t)L * CDIM, n1_b + (size_t)L * CDIM, L ? 2 : 1);

        // MLP up: gelu((M x 192) @ (192 x 768) + b)
        mma_gemm_kernel<1><<<dim3(FFN / 64, MTOK / 128), 256>>>(
            gx, w1 + (size_t)L * CDIM * FFN, b1 + (size_t)L * FFN,
            gh, CDIM, FFN);

        // MLP down: (M x 768) @ (768 x 192) + b
        mma_gemm_kernel<0><<<dim3(CDIM / 64, MTOK / 128), 256>>>(
            gh, w2 + (size_t)L * FFN * CDIM, b2 + (size_t)L * CDIM,
            gtmp, FFN, CDIM);

        // x += LN(mlp_out)
        ln_add_kernel<<<(MTOK * 32 + 255) / 256, 256>>>(
            gtmp, n2_g + (size_t)L * CDIM, n2_b + (size_t)L * CDIM, 0);
    }

    cudaMemcpyAsync(d_out, gx, xbytes, cudaMemcpyDeviceToDevice);
}

// round 3
// speedup vs baseline: 2.0516x; 1.1361x over previous
#include <cuda_runtime.h>
#include <cuda_bf16.h>
#include <math.h>

#define MTOK   73728
#define CDIM   192
#define NHEAD  6
#define HD     32
#define NTOK   144
#define NWIN   512
#define TWIN   32
#define NWW    16
#define NB     3312
#define QKVN   576
#define FFN    768

__device__ float g_x  [(size_t)MTOK * CDIM];
__device__ float g_xw [(size_t)MTOK * CDIM];
__device__ float g_qkv[(size_t)MTOK * QKVN];
__device__ float g_ao [(size_t)MTOK * CDIM];
__device__ float g_tmp[(size_t)MTOK * CDIM];
__device__ float g_h  [(size_t)MTOK * FFN];
__device__ float g_bm [(size_t)2 * TWIN * NHEAD * NTOK * NTOK];

// ---------------------------------------------------------------------------
// Dense (relative-position bias + shift mask)
// ---------------------------------------------------------------------------
__global__ void biasmask_kernel(const float* __restrict__ table) {
    size_t idx = (size_t)blockIdx.x * blockDim.x + threadIdx.x;
    size_t total = (size_t)2 * TWIN * NHEAD * NTOK * NTOK;
    if (idx >= total) return;
    int m = idx % NTOK; size_t r = idx / NTOK;
    int n = r % NTOK;   r /= NTOK;
    int head = r % NHEAD; r /= NHEAD;
    int t = r % TWIN;   int L = (int)(r / TWIN);
    int z1 = n / 72, h1 = (n % 72) / 12, w1 = n % 12;
    int z2 = m / 72, h2 = (m % 72) / 12, w2 = m % 12;
    int pos = 828 * (z1 + 2 * z2) + 23 * (h1 + 6 * h2) + (w1 - w2 + 11);
    float v = table[(((size_t)L * NB + pos) * TWIN + t) * NHEAD + head];
    if (L == 1) {
        int tz = t / 8, th = t % 8;
        int idn = (((tz * 2 + z1) >= 1) ? 2 : 0) + (((th * 6 + h1) >= 3) ? 1 : 0);
        int idm = (((tz * 2 + z2) >= 1) ? 2 : 0) + (((th * 6 + h2) >= 3) ? 1 : 0);
        if (idn != idm) v += -10000.0f;
    }
    g_bm[idx] = v;
}

// Window gather: xw[r][:] = x[src(r)][:]
__global__ void gather_kernel(int rolled) {
    int idx = blockIdx.x * blockDim.x + threadIdx.x;
    if (idx >= MTOK * 48) return;
    int c4 = idx % 48;
    int r  = idx / 48;
    int n   = r % NTOK;
    int win = r / NTOK;
    int l = win % NWW, t = win / NWW;
    int tz = t / 8, th = t % 8;
    int z1 = n / 72, h1 = (n % 72) / 12, w1 = n % 12;
    int zr = tz * 2 + z1, hr = th * 6 + h1, wr = l * 12 + w1;
    int z, hh, ww;
    if (rolled) { z = (zr + 7) & 7; hh = (hr + 45) % 48; ww = (wr + 186) % 192; }
    else        { z = zr; hh = hr; ww = wr; }
    size_t p = ((size_t)z * 48 + hh) * 192 + ww;
    reinterpret_cast<float4*>(g_xw)[(size_t)r * 48 + c4] =
        reinterpret_cast<const float4*>(g_x)[p * 48 + c4];
}

__device__ __forceinline__ float gelu_exact(float v) {
    return 0.5f * v * (1.0f + erff(v * 0.70710678118654752f));
}

__device__ __forceinline__ unsigned f2tf32(float x) {
    unsigned r;
    asm("cvt.rna.tf32.f32 %0, %1;" : "=r"(r) : "f"(x));
    return r;
}
__device__ __forceinline__ float f2tf32f(float x) {
    return __uint_as_float(f2tf32(x));
}

__device__ __forceinline__ void mma_tf32(float* d, const unsigned* a, const unsigned* b) {
    asm volatile(
        "mma.sync.aligned.m16n8k8.row.col.f32.tf32.tf32.f32 "
        "{%0,%1,%2,%3}, {%4,%5,%6,%7}, {%8,%9}, {%0,%1,%2,%3};\n"
        : "+f"(d[0]), "+f"(d[1]), "+f"(d[2]), "+f"(d[3])
        : "r"(a[0]), "r"(a[1]), "r"(a[2]), "r"(a[3]),
          "r"(b[0]), "r"(b[1]));
}

// ---------------------------------------------------------------------------
// tf32 tensor-core GEMM with register-prefetch double buffering.
// C = A(MxK,rm) * B(KxN,rm) + bias [, GELU]; BM=128, BN=64, BK=16; 256 thr.
// ---------------------------------------------------------------------------
template <int EPI>
__global__ void __launch_bounds__(256)
mma_gemm_kernel(const float* __restrict__ A,
                const float* __restrict__ B,
                const float* __restrict__ bias,
                float* __restrict__ Cm,
                int K, int Nn) {
    __shared__ unsigned As[128 * 20];
    __shared__ unsigned Bs[16 * 68];

    const int tid  = threadIdx.x;
    const int lane = tid & 31;
    const int wid  = tid >> 5;
    const int wm   = wid >> 1;
    const int wn   = wid & 1;
    const int g    = lane >> 2;
    const int tg   = lane & 3;
    const int m0   = blockIdx.y * 128;
    const int n0   = blockIdx.x * 64;

    const int arow = tid >> 2, ac4 = tid & 3;          // A: 2 float4/thread
    const int brow = tid >> 4, bc4 = tid & 15;         // B: 1 float4/thread
    const float* ApA = A + (size_t)(m0 + arow) * K + ac4 * 4;
    const float* ApB = A + (size_t)(m0 + arow + 64) * K + ac4 * 4;
    const float* Bp  = B + (size_t)brow * Nn + n0 + bc4 * 4;

    float acc[2][4][4];
    #pragma unroll
    for (int mt = 0; mt < 2; mt++)
        #pragma unroll
        for (int nt = 0; nt < 4; nt++)
            #pragma unroll
            for (int i = 0; i < 4; i++) acc[mt][nt][i] = 0.0f;

    float4 ra0 = *reinterpret_cast<const float4*>(ApA);
    float4 ra1 = *reinterpret_cast<const float4*>(ApB);
    float4 rb  = *reinterpret_cast<const float4*>(Bp);

    for (int k0 = 0; k0 < K; k0 += 16) {
        // commit prefetched tile to smem (with tf32 cvt)
        {
            unsigned* d0 = &As[arow * 20 + ac4 * 4];
            d0[0] = f2tf32(ra0.x); d0[1] = f2tf32(ra0.y);
            d0[2] = f2tf32(ra0.z); d0[3] = f2tf32(ra0.w);
            unsigned* d1 = &As[(arow + 64) * 20 + ac4 * 4];
            d1[0] = f2tf32(ra1.x); d1[1] = f2tf32(ra1.y);
            d1[2] = f2tf32(ra1.z); d1[3] = f2tf32(ra1.w);
            unsigned* d2 = &Bs[brow * 68 + bc4 * 4];
            d2[0] = f2tf32(rb.x);  d2[1] = f2tf32(rb.y);
            d2[2] = f2tf32(rb.z);  d2[3] = f2tf32(rb.w);
        }
        __syncthreads();
        // prefetch next tile while mma runs on current
        if (k0 + 16 < K) {
            ra0 = *reinterpret_cast<const float4*>(ApA + k0 + 16);
            ra1 = *reinterpret_cast<const float4*>(ApB + k0 + 16);
            rb  = *reinterpret_cast<const float4*>(Bp + (size_t)(k0 + 16) * Nn);
        }
        #pragma unroll
        for (int ks = 0; ks < 2; ks++) {
            const int kk = ks * 8;
            unsigned af[2][4], bf[4][2];
            #pragma unroll
            for (int mt = 0; mt < 2; mt++) {
                int rbse = wm * 32 + mt * 16;
                af[mt][0] = As[(rbse + g)     * 20 + kk + tg];
                af[mt][1] = As[(rbse + 8 + g) * 20 + kk + tg];
                af[mt][2] = As[(rbse + g)     * 20 + kk + tg + 4];
                af[mt][3] = As[(rbse + 8 + g) * 20 + kk + tg + 4];
            }
            #pragma unroll
            for (int nt = 0; nt < 4; nt++) {
                int cb = wn * 32 + nt * 8;
                bf[nt][0] = Bs[(kk + tg)     * 68 + cb + g];
                bf[nt][1] = Bs[(kk + 4 + tg) * 68 + cb + g];
            }
            #pragma unroll
            for (int mt = 0; mt < 2; mt++)
                #pragma unroll
                for (int nt = 0; nt < 4; nt++)
                    mma_tf32(acc[mt][nt], af[mt], bf[nt]);
        }
        __syncthreads();
    }

    #pragma unroll
    for (int mt = 0; mt < 2; mt++) {
        int r0 = m0 + wm * 32 + mt * 16 + g;
        #pragma unroll
        for (int nt = 0; nt < 4; nt++) {
            int c = n0 + wn * 32 + nt * 8 + tg * 2;
            float b0 = bias[c], b1 = bias[c + 1];
            float v0 = acc[mt][nt][0] + b0;
            float v1 = acc[mt][nt][1] + b1;
            float v2 = acc[mt][nt][2] + b0;
            float v3 = acc[mt][nt][3] + b1;
            if (EPI == 1) {
                v0 = gelu_exact(v0); v1 = gelu_exact(v1);
                v2 = gelu_exact(v2); v3 = gelu_exact(v3);
            }
            *reinterpret_cast<float2*>(Cm + (size_t)r0 * Nn + c)       = make_float2(v0, v1);
            *reinterpret_cast<float2*>(Cm + (size_t)(r0 + 8) * Nn + c) = make_float2(v2, v3);
        }
    }
}

// ---------------------------------------------------------------------------
// Tensor-core window attention. Block = (window, head), 128 threads / 4 warps.
// S = Q Kᵀ (144x144x32) and O = P V (144x32x144) via m16n8k8 tf32 mma.
// Scores in registers; softmax across the 4-lane quad owning each row;
// P staged per-warp through smem scratch (stride 148 -> conflict-free).
// ---------------------------------------------------------------------------
#define SCR_STRIDE 148

__global__ void __launch_bounds__(128) attn_mma_kernel(int L) {
    const int win  = blockIdx.x;
    const int head = blockIdx.y;
    const int t    = win >> 4;
    extern __shared__ float sm[];
    float* qs  = sm;                       // 144*32 (tf32 bits, pre-scaled)
    float* ks  = qs + NTOK * HD;           // 144*32
    float* vs  = ks + NTOK * HD;           // 144*32
    float* scr = vs + NTOK * HD;           // 4 * 16 * 148

    const int tid  = threadIdx.x;
    const int lane = tid & 31;
    const int wid  = tid >> 5;
    const int g    = lane >> 2;
    const int tg   = lane & 3;

    // load q/k/v for this (window, head); scale+cvt q, cvt k/v
    const float* base = g_qkv + (size_t)win * NTOK * QKVN;
    const int hc4 = head * 8;
    for (int idx = tid; idx < NTOK * 8; idx += 128) {
        int row = idx >> 3, j = idx & 7;
        const float4* rp = reinterpret_cast<const float4*>(base + (size_t)row * QKVN);
        float4 q4 = rp[hc4 + j];
        float4 k4 = rp[48 + hc4 + j];
        float4 v4 = rp[96 + hc4 + j];
        const float sc = 0.17677669529663687f;
        reinterpret_cast<float4*>(qs)[row * 8 + j] =
            make_float4(f2tf32f(q4.x * sc), f2tf32f(q4.y * sc),
                        f2tf32f(q4.z * sc), f2tf32f(q4.w * sc));
        reinterpret_cast<float4*>(ks)[row * 8 + j] =
            make_float4(f2tf32f(k4.x), f2tf32f(k4.y), f2tf32f(k4.z), f2tf32f(k4.w));
        reinterpret_cast<float4*>(vs)[row * 8 + j] =
            make_float4(f2tf32f(v4.x), f2tf32f(v4.y), f2tf32f(v4.z), f2tf32f(v4.w));
    }
    __syncthreads();

    const float* bmb = g_bm + (((size_t)L * TWIN + t) * NHEAD + head) * NTOK * NTOK;
    float* wscr = scr + wid * 16 * SCR_STRIDE;

    for (int mt = wid; mt < 9; mt += 4) {
        const int rb = mt * 16;

        // Q fragments for this 16-row tile (K = 32 -> 4 k-steps)
        unsigned aq[4][4];
        #pragma unroll
        for (int kk = 0; kk < 4; kk++) {
            const int kc = kk * 8;
            aq[kk][0] = __float_as_uint(qs[(rb + g)     * HD + kc + tg]);
            aq[kk][1] = __float_as_uint(qs[(rb + 8 + g) * HD + kc + tg]);
            aq[kk][2] = __float_as_uint(qs[(rb + g)     * HD + kc + tg + 4]);
            aq[kk][3] = __float_as_uint(qs[(rb + 8 + g) * HD + kc + tg + 4]);
        }

        // S = Q K^T + bias : 18 n-tiles of 8 cols
        float sacc[18][4];
        #pragma unroll
        for (int nt = 0; nt < 18; nt++) {
            sacc[nt][0] = sacc[nt][1] = sacc[nt][2] = sacc[nt][3] = 0.0f;
            const int cb = nt * 8;
            #pragma unroll
            for (int kk = 0; kk < 4; kk++) {
                const int kc = kk * 8;
                unsigned bf[2];
                bf[0] = __float_as_uint(ks[(cb + g) * HD + kc + tg]);
                bf[1] = __float_as_uint(ks[(cb + g) * HD + kc + tg + 4]);
                mma_tf32(sacc[nt], aq[kk], bf);
            }
            // bias at accumulator coordinates
            const float2 bA = *reinterpret_cast<const float2*>(
                bmb + (size_t)(rb + g) * NTOK + cb + tg * 2);
            const float2 bB = *reinterpret_cast<const float2*>(
                bmb + (size_t)(rb + 8 + g) * NTOK + cb + tg * 2);
            sacc[nt][0] += bA.x; sacc[nt][1] += bA.y;
            sacc[nt][2] += bB.x; sacc[nt][3] += bB.y;
        }

        // softmax over each full row (row g in [0..1], row g+8 in [2..3])
        float mxA = -1e30f, mxB = -1e30f;
        #pragma unroll
        for (int nt = 0; nt < 18; nt++) {
            mxA = fmaxf(mxA, fmaxf(sacc[nt][0], sacc[nt][1]));
            mxB = fmaxf(mxB, fmaxf(sacc[nt][2], sacc[nt][3]));
        }
        #pragma unroll
        for (int o = 1; o <= 2; o <<= 1) {
            mxA = fmaxf(mxA, __shfl_xor_sync(0xFFFFFFFFu, mxA, o));
            mxB = fmaxf(mxB, __shfl_xor_sync(0xFFFFFFFFu, mxB, o));
        }
        float smA = 0.0f, smB = 0.0f;
        #pragma unroll
        for (int nt = 0; nt < 18; nt++) {
            sacc[nt][0] = __expf(sacc[nt][0] - mxA);
            sacc[nt][1] = __expf(sacc[nt][1] - mxA);
            sacc[nt][2] = __expf(sacc[nt][2] - mxB);
            sacc[nt][3] = __expf(sacc[nt][3] - mxB);
            smA += sacc[nt][0] + sacc[nt][1];
            smB += sacc[nt][2] + sacc[nt][3];
        }
        #pragma unroll
        for (int o = 1; o <= 2; o <<= 1) {
            smA += __shfl_xor_sync(0xFFFFFFFFu, smA, o);
            smB += __shfl_xor_sync(0xFFFFFFFFu, smB, o);
        }
        const float invA = 1.0f / smA;
        const float invB = 1.0f / smB;

        // stage P (unnormalized, tf32) into per-warp scratch
        #pragma unroll
        for (int nt = 0; nt < 18; nt++) {
            const int cb = nt * 8 + tg * 2;
            *reinterpret_cast<float2*>(&wscr[g * SCR_STRIDE + cb]) =
                make_float2(f2tf32f(sacc[nt][0]), f2tf32f(sacc[nt][1]));
            *reinterpret_cast<float2*>(&wscr[(g + 8) * SCR_STRIDE + cb]) =
                make_float2(f2tf32f(sacc[nt][2]), f2tf32f(sacc[nt][3]));
        }
        __syncwarp();

        // O = P V : K = 144 -> 18 k-steps, N = 32 -> 4 n-tiles
        float oacc[4][4];
        #pragma unroll
        for (int nt = 0; nt < 4; nt++)
            oacc[nt][0] = oacc[nt][1] = oacc[nt][2] = oacc[nt][3] = 0.0f;
        #pragma unroll
        for (int kk = 0; kk < 18; kk++) {
            const int kc = kk * 8;
            unsigned ap[4];
            ap[0] = __float_as_uint(wscr[g * SCR_STRIDE + kc + tg]);
            ap[1] = __float_as_uint(wscr[(g + 8) * SCR_STRIDE + kc + tg]);
            ap[2] = __float_as_uint(wscr[g * SCR_STRIDE + kc + tg + 4]);
            ap[3] = __float_as_uint(wscr[(g + 8) * SCR_STRIDE + kc + tg + 4]);
            #pragma unroll
            for (int nt = 0; nt < 4; nt++) {
                unsigned bf[2];
                bf[0] = __float_as_uint(vs[(kc + tg)     * HD + nt * 8 + g]);
                bf[1] = __float_as_uint(vs[(kc + tg + 4) * HD + nt * 8 + g]);
                mma_tf32(oacc[nt], ap, bf);
            }
        }
        __syncwarp();

        // write O (normalize rows here)
        #pragma unroll
        for (int nt = 0; nt < 4; nt++) {
            const int c = nt * 8 + tg * 2;
            float* opA = g_ao + ((size_t)win * NTOK + rb + g) * CDIM + head * HD + c;
            float* opB = g_ao + ((size_t)win * NTOK + rb + 8 + g) * CDIM + head * HD + c;
            *reinterpret_cast<float2*>(opA) =
                make_float2(oacc[nt][0] * invA, oacc[nt][1] * invA);
            *reinterpret_cast<float2*>(opB) =
                make_float2(oacc[nt][2] * invB, oacc[nt][3] * invB);
        }
    }
}

// ---------------------------------------------------------------------------
// LayerNorm + residual: x[p] += LN(y[r])*g + b. mode 0: p=r; 1: un-window;
// 2: un-window + un-roll. One warp per row.
// ---------------------------------------------------------------------------
__global__ void ln_add_kernel(const float* __restrict__ y,
                              const float* __restrict__ g,
                              const float* __restrict__ b,
                              int mode) {
    int w = (blockIdx.x * blockDim.x + threadIdx.x) >> 5;
    int lane = threadIdx.x & 31;
    if (w >= MTOK) return;
    size_t p;
    if (mode == 0) {
        p = (size_t)w;
    } else {
        int n = w % NTOK, win = w / NTOK;
        int l = win % NWW, t = win / NWW;
        int tz = t / 8, th = t % 8;
        int z1 = n / 72, h1 = (n % 72) / 12, w1 = n % 12;
        int zr = tz * 2 + z1, hr = th * 6 + h1, wr = l * 12 + w1;
        int z, hh, ww;
        if (mode == 2) { z = (zr + 7) & 7; hh = (hr + 45) % 48; ww = (wr + 186) % 192; }
        else           { z = zr; hh = hr; ww = wr; }
        p = ((size_t)z * 48 + hh) * 192 + ww;
    }
    const float* yr = y + (size_t)w * CDIM;
    float v[6];
    float sum = 0.0f;
    #pragma unroll
    for (int i = 0; i < 6; i++) { v[i] = yr[lane + 32 * i]; sum += v[i]; }
    #pragma unroll
    for (int o = 16; o; o >>= 1) sum += __shfl_xor_sync(0xFFFFFFFFu, sum, o);
    float mu = sum * (1.0f / 192.0f);
    float var = 0.0f;
    #pragma unroll
    for (int i = 0; i < 6; i++) { float d = v[i] - mu; var += d * d; }
    #pragma unroll
    for (int o = 16; o; o >>= 1) var += __shfl_xor_sync(0xFFFFFFFFu, var, o);
    var *= (1.0f / 192.0f);
    float rs = rsqrtf(var + 1e-5f);
    float* xp = g_x + p * CDIM;
    #pragma unroll
    for (int i = 0; i < 6; i++) {
        int c = lane + 32 * i;
        xp[c] += (v[i] - mu) * rs * g[c] + b[c];
    }
}

extern "C" void kernel_launch(void* const* d_in, const int* in_sizes, int n_in,
                              void* d_out, int out_size) {
    const float* x_in       = (const float*)d_in[0];
    const float* qkv_w      = (const float*)d_in[1];
    const float* qkv_b      = (const float*)d_in[2];
    const float* proj_w     = (const float*)d_in[3];
    const float* proj_b     = (const float*)d_in[4];
    const float* bias_table = (const float*)d_in[5];
    const float* n1_g       = (const float*)d_in[6];
    const float* n1_b       = (const float*)d_in[7];
    const float* n2_g       = (const float*)d_in[8];
    const float* n2_b       = (const float*)d_in[9];
    const float* w1         = (const float*)d_in[10];
    const float* b1         = (const float*)d_in[11];
    const float* w2         = (const float*)d_in[12];
    const float* b2         = (const float*)d_in[13];
    // d_in[14..16] = Z,H,W scalars (fixed 8,48,192)

    float *gx, *gxw, *gqkv, *gao, *gtmp, *gh;
    cudaGetSymbolAddress((void**)&gx,   g_x);
    cudaGetSymbolAddress((void**)&gxw,  g_xw);
    cudaGetSymbolAddress((void**)&gqkv, g_qkv);
    cudaGetSymbolAddress((void**)&gao,  g_ao);
    cudaGetSymbolAddress((void**)&gtmp, g_tmp);
    cudaGetSymbolAddress((void**)&gh,   g_h);

    const size_t xbytes = (size_t)MTOK * CDIM * sizeof(float);
    cudaMemcpyAsync(gx, x_in, xbytes, cudaMemcpyDeviceToDevice);

    {
        size_t total = (size_t)2 * TWIN * NHEAD * NTOK * NTOK;
        biasmask_kernel<<<(unsigned)((total + 255) / 256), 256>>>(bias_table);
    }

    const int ATTN_SMEM = (3 * NTOK * HD + 4 * 16 * SCR_STRIDE) * (int)sizeof(float); // 93184 B
    cudaFuncSetAttribute(attn_mma_kernel, cudaFuncAttributeMaxDynamicSharedMemorySize, ATTN_SMEM);

    for (int L = 0; L < 2; L++) {
        gather_kernel<<<(MTOK * 48 + 255) / 256, 256>>>(L);

        // QKV: (M x 192) @ (192 x 576) + b
        mma_gemm_kernel<0><<<dim3(QKVN / 64, MTOK / 128), 256>>>(
            gxw, qkv_w + (size_t)L * CDIM * QKVN, qkv_b + (size_t)L * QKVN,
            gqkv, CDIM, QKVN);

        attn_mma_kernel<<<dim3(NWIN, NHEAD), 128, ATTN_SMEM>>>(L);

        // proj: (M x 192) @ (192 x 192) + b
        mma_gemm_kernel<0><<<dim3(CDIM / 64, MTOK / 128), 256>>>(
            gao, proj_w + (size_t)L * CDIM * CDIM, proj_b + (size_t)L * CDIM,
            gtmp, CDIM, CDIM);

        // x += LN(un-window(proj_out))
        ln_add_kernel<<<(MTOK * 32 + 255) / 256, 256>>>(
            gtmp, n1_g + (size_t)L * CDIM, n1_b + (size_t)L * CDIM, L ? 2 : 1);

        // MLP up: gelu((M x 192) @ (192 x 768) + b)
        mma_gemm_kernel<1><<<dim3(FFN / 64, MTOK / 128), 256>>>(
            gx, w1 + (size_t)L * CDIM * FFN, b1 + (size_t)L * FFN,
            gh, CDIM, FFN);

        // MLP down: (M x 768) @ (768 x 192) + b
        mma_gemm_kernel<0><<<dim3(CDIM / 64, MTOK / 128), 256>>>(
            gh, w2 + (size_t)L * FFN * CDIM, b2 + (size_t)L * CDIM,
            gtmp, FFN, CDIM);

        // x += LN(mlp_out)
        ln_add_kernel<<<(MTOK * 32 + 255) / 256, 256>>>(
            gtmp, n2_g + (size_t)L * CDIM, n2_b + (size_t)L * CDIM, 0);
    }

    cudaMemcpyAsync(d_out, gx, xbytes, cudaMemcpyDeviceToDevice);
}

// round 4
// speedup vs baseline: 2.9875x; 1.4562x over previous
#include <cuda_runtime.h>
#include <cuda_bf16.h>
#include <math.h>

#define MTOK   73728
#define CDIM   192
#define NHEAD  6
#define HD     32
#define NTOK   144
#define NWIN   512
#define TWIN   32
#define NWW    16
#define NB     3312
#define QKVN   576
#define FFN    768

__device__ float g_x  [(size_t)MTOK * CDIM];
__device__ float g_qkv[(size_t)MTOK * QKVN];
__device__ float g_ao [(size_t)MTOK * CDIM];
__device__ float g_tmp[(size_t)MTOK * CDIM];
__device__ float g_h  [(size_t)MTOK * FFN];
__device__ float g_bm [(size_t)2 * TWIN * NHEAD * NTOK * NTOK];

// ---------------------------------------------------------------------------
// helpers
// ---------------------------------------------------------------------------
__device__ __forceinline__ unsigned f2tf32(float x) {
    unsigned r;
    asm("cvt.rna.tf32.f32 %0, %1;" : "=r"(r) : "f"(x));
    return r;
}
__device__ __forceinline__ float f2tf32f(float x) { return __uint_as_float(f2tf32(x)); }

__device__ __forceinline__ void mma_tf32(float* d, const unsigned* a, const unsigned* b) {
    asm volatile(
        "mma.sync.aligned.m16n8k8.row.col.f32.tf32.tf32.f32 "
        "{%0,%1,%2,%3}, {%4,%5,%6,%7}, {%8,%9}, {%0,%1,%2,%3};\n"
        : "+f"(d[0]), "+f"(d[1]), "+f"(d[2]), "+f"(d[3])
        : "r"(a[0]), "r"(a[1]), "r"(a[2]), "r"(a[3]),
          "r"(b[0]), "r"(b[1]));
}

__device__ __forceinline__ unsigned smaddr(const void* p) {
    return (unsigned)__cvta_generic_to_shared(p);
}
#define CPA16(dst, src) asm volatile("cp.async.cg.shared.global [%0], [%1], 16;" :: "r"(dst), "l"(src))
#define CPCOMMIT()      asm volatile("cp.async.commit_group;")
#define CPWAIT1()       asm volatile("cp.async.wait_group 1;")

__device__ __forceinline__ float gelu_exact(float v) {
    return 0.5f * v * (1.0f + erff(v * 0.70710678118654752f));
}

// ---------------------------------------------------------------------------
// Dense (relative-position bias + shift mask)
// ---------------------------------------------------------------------------
__global__ void biasmask_kernel(const float* __restrict__ table) {
    size_t idx = (size_t)blockIdx.x * blockDim.x + threadIdx.x;
    size_t total = (size_t)2 * TWIN * NHEAD * NTOK * NTOK;
    if (idx >= total) return;
    int m = idx % NTOK; size_t r = idx / NTOK;
    int n = r % NTOK;   r /= NTOK;
    int head = r % NHEAD; r /= NHEAD;
    int t = r % TWIN;   int L = (int)(r / TWIN);
    int z1 = n / 72, h1 = (n % 72) / 12, w1 = n % 12;
    int z2 = m / 72, h2 = (m % 72) / 12, w2 = m % 12;
    int pos = 828 * (z1 + 2 * z2) + 23 * (h1 + 6 * h2) + (w1 - w2 + 11);
    float v = table[(((size_t)L * NB + pos) * TWIN + t) * NHEAD + head];
    if (L == 1) {
        int tz = t / 8, th = t % 8;
        int idn = (((tz * 2 + z1) >= 1) ? 2 : 0) + (((th * 6 + h1) >= 3) ? 1 : 0);
        int idm = (((tz * 2 + z2) >= 1) ? 2 : 0) + (((th * 6 + h2) >= 3) ? 1 : 0);
        if (idn != idm) v += -10000.0f;
    }
    g_bm[idx] = v;
}

// ---------------------------------------------------------------------------
// tf32 GEMM, cp.async 3-stage pipeline, BK=32, BM=128, BN=64, 256 threads.
// C = A(MxK) * B(KxN) + bias [, GELU].  GATHER=1: A rows remapped (window
// gather of g_x), `rolled` selects the shifted mapping.
// smem: As 3 x [128][36] fp32, Bs 3 x [32][72] fp32 (both conflict-free pads).
// ---------------------------------------------------------------------------
#define ASTG (128 * 36)
#define BSTG (32 * 72)
#define GEMM_SMEM ((3 * ASTG + 3 * BSTG) * 4)

template <int EPI, int GATHER>
__global__ void __launch_bounds__(256, 2)
mma_gemm_kernel(const float* __restrict__ A,
                const float* __restrict__ B,
                const float* __restrict__ bias,
                float* __restrict__ Cm,
                int K, int Nn, int rolled) {
    extern __shared__ float dsm[];
    float* As = dsm;
    float* Bs = dsm + 3 * ASTG;

    const int tid  = threadIdx.x;
    const int lane = tid & 31;
    const int wid  = tid >> 5;
    const int wm   = wid >> 1;
    const int wn   = wid & 1;
    const int g    = lane >> 2;
    const int tg   = lane & 3;
    const int m0   = blockIdx.y * 128;
    const int n0   = blockIdx.x * 64;

    // copy-role indices (fixed across k)
    const int arow0 = tid >> 3;        // + 32*i, i<4
    const int akc4  = tid & 7;
    const int brow0 = tid >> 4;        // + 16*i, i<2
    const int bc4   = tid & 15;

    const float* aSrc[4];
    #pragma unroll
    for (int i = 0; i < 4; i++) {
        int r = m0 + arow0 + 32 * i;
        size_t p;
        if (GATHER) {
            int n = r % NTOK, win = r / NTOK;
            int l = win % NWW, t = win / NWW;
            int tz = t / 8, th = t % 8;
            int z1 = n / 72, h1 = (n % 72) / 12, w1 = n % 12;
            int zr = tz * 2 + z1, hr = th * 6 + h1, wr = l * 12 + w1;
            int z, hh, ww;
            if (rolled) { z = (zr + 7) & 7; hh = (hr + 45) % 48; ww = (wr + 186) % 192; }
            else        { z = zr; hh = hr; ww = wr; }
            p = ((size_t)z * 48 + hh) * 192 + ww;
        } else {
            p = (size_t)r;
        }
        aSrc[i] = A + p * K + akc4 * 4;
    }
    const float* bSrc = B + (size_t)brow0 * Nn + n0 + bc4 * 4;

    float acc[2][4][4];
    #pragma unroll
    for (int mt = 0; mt < 2; mt++)
        #pragma unroll
        for (int nt = 0; nt < 4; nt++)
            #pragma unroll
            for (int i = 0; i < 4; i++) acc[mt][nt][i] = 0.0f;

    // prologue: stages 0,1
    #pragma unroll
    for (int s = 0; s < 2; s++) {
        float* as = As + s * ASTG;
        float* bs = Bs + s * BSTG;
        const int k0 = s * 32;
        #pragma unroll
        for (int i = 0; i < 4; i++)
            CPA16(smaddr(as + (arow0 + 32 * i) * 36 + akc4 * 4), aSrc[i] + k0);
        #pragma unroll
        for (int i = 0; i < 2; i++)
            CPA16(smaddr(bs + (brow0 + 16 * i) * 72 + bc4 * 4),
                  bSrc + (size_t)(k0 + 16 * i) * Nn);
        CPCOMMIT();
    }

    const int iters = K >> 5;
    int cur = 0;
    for (int it = 0; it < iters; it++) {
        CPWAIT1();
        __syncthreads();

        // issue next stage (into the slot consumed last iteration)
        const int k0n = (it + 2) << 5;
        if (k0n < K) {
            const int stg = (cur + 2) % 3;
            float* as = As + stg * ASTG;
            float* bs = Bs + stg * BSTG;
            #pragma unroll
            for (int i = 0; i < 4; i++)
                CPA16(smaddr(as + (arow0 + 32 * i) * 36 + akc4 * 4), aSrc[i] + k0n);
            #pragma unroll
            for (int i = 0; i < 2; i++)
                CPA16(smaddr(bs + (brow0 + 16 * i) * 72 + bc4 * 4),
                      bSrc + (size_t)(k0n + 16 * i) * Nn);
        }
        CPCOMMIT();

        const float* as = As + cur * ASTG;
        const float* bs = Bs + cur * BSTG;
        #pragma unroll
        for (int ks = 0; ks < 4; ks++) {
            const int kk = ks * 8;
            unsigned af[2][4], bf[4][2];
            #pragma unroll
            for (int mt = 0; mt < 2; mt++) {
                int rbse = wm * 32 + mt * 16;
                af[mt][0] = f2tf32(as[(rbse + g)     * 36 + kk + tg]);
                af[mt][1] = f2tf32(as[(rbse + 8 + g) * 36 + kk + tg]);
                af[mt][2] = f2tf32(as[(rbse + g)     * 36 + kk + tg + 4]);
                af[mt][3] = f2tf32(as[(rbse + 8 + g) * 36 + kk + tg + 4]);
            }
            #pragma unroll
            for (int nt = 0; nt < 4; nt++) {
                int cb = wn * 32 + nt * 8;
                bf[nt][0] = f2tf32(bs[(kk + tg)     * 72 + cb + g]);
                bf[nt][1] = f2tf32(bs[(kk + 4 + tg) * 72 + cb + g]);
            }
            #pragma unroll
            for (int mt = 0; mt < 2; mt++)
                #pragma unroll
                for (int nt = 0; nt < 4; nt++)
                    mma_tf32(acc[mt][nt], af[mt], bf[nt]);
        }
        cur = (cur + 1) % 3;
    }

    #pragma unroll
    for (int mt = 0; mt < 2; mt++) {
        int r0 = m0 + wm * 32 + mt * 16 + g;
        #pragma unroll
        for (int nt = 0; nt < 4; nt++) {
            int c = n0 + wn * 32 + nt * 8 + tg * 2;
            float b0 = bias[c], b1 = bias[c + 1];
            float v0 = acc[mt][nt][0] + b0;
            float v1 = acc[mt][nt][1] + b1;
            float v2 = acc[mt][nt][2] + b0;
            float v3 = acc[mt][nt][3] + b1;
            if (EPI == 1) {
                v0 = gelu_exact(v0); v1 = gelu_exact(v1);
                v2 = gelu_exact(v2); v3 = gelu_exact(v3);
            }
            *reinterpret_cast<float2*>(Cm + (size_t)r0 * Nn + c)       = make_float2(v0, v1);
            *reinterpret_cast<float2*>(Cm + (size_t)(r0 + 8) * Nn + c) = make_float2(v2, v3);
        }
    }
}

// ---------------------------------------------------------------------------
// Tensor-core window attention v2.
// Conflict-free pads: ks stride 36 (4g+tg), vs stride 40 (8tg+g),
// P scratch stride 76 (12g+tg). Q fragments loaded straight from gmem.
// smem 62 KB -> 3 blocks/SM.
// ---------------------------------------------------------------------------
#define KS_S  36
#define VS_S  40
#define SCR_S 76
#define ATTN_SMEM ((NTOK * KS_S + NTOK * VS_S + 4 * 16 * SCR_S) * 4)

__global__ void __launch_bounds__(128, 3) attn_mma_kernel(int L) {
    const int win  = blockIdx.x;
    const int head = blockIdx.y;
    const int t    = win >> 4;
    extern __shared__ float sm[];
    float* ks  = sm;                        // [144][36]
    float* vs  = ks + NTOK * KS_S;          // [144][40]
    float* scr = vs + NTOK * VS_S;          // 4 x [16][76]

    const int tid  = threadIdx.x;
    const int lane = tid & 31;
    const int wid  = tid >> 5;
    const int g    = lane >> 2;
    const int tg   = lane & 3;

    // cooperative K/V load (cvt to tf32 at store)
    const float* base = g_qkv + (size_t)win * NTOK * QKVN;
    const int hc4 = head * 8;
    for (int idx = tid; idx < NTOK * 8; idx += 128) {
        int row = idx >> 3, j = idx & 7;
        const float4* rp = reinterpret_cast<const float4*>(base + (size_t)row * QKVN);
        float4 k4 = rp[48 + hc4 + j];
        float4 v4 = rp[96 + hc4 + j];
        *reinterpret_cast<float4*>(&ks[row * KS_S + j * 4]) =
            make_float4(f2tf32f(k4.x), f2tf32f(k4.y), f2tf32f(k4.z), f2tf32f(k4.w));
        *reinterpret_cast<float4*>(&vs[row * VS_S + j * 4]) =
            make_float4(f2tf32f(v4.x), f2tf32f(v4.y), f2tf32f(v4.z), f2tf32f(v4.w));
    }
    __syncthreads();

    const float* bmb = g_bm + (((size_t)L * TWIN + t) * NHEAD + head) * NTOK * NTOK;
    float* wscr = scr + wid * 16 * SCR_S;
    const float sc = 0.17677669529663687f;   // 1/sqrt(32)

    for (int mt = wid; mt < 9; mt += 4) {
        const int rb = mt * 16;

        // Q fragments direct from gmem (L1-cached), scaled + tf32
        const float* qA = g_qkv + (size_t)(win * NTOK + rb + g) * QKVN + head * HD;
        const float* qB = g_qkv + (size_t)(win * NTOK + rb + 8 + g) * QKVN + head * HD;
        unsigned aq[4][4];
        #pragma unroll
        for (int kk4 = 0; kk4 < 4; kk4++) {
            const int kc = kk4 * 8;
            aq[kk4][0] = f2tf32(qA[kc + tg] * sc);
            aq[kk4][1] = f2tf32(qB[kc + tg] * sc);
            aq[kk4][2] = f2tf32(qA[kc + tg + 4] * sc);
            aq[kk4][3] = f2tf32(qB[kc + tg + 4] * sc);
        }

        // S = Q K^T + bias
        float sacc[18][4];
        #pragma unroll
        for (int nt = 0; nt < 18; nt++) {
            sacc[nt][0] = sacc[nt][1] = sacc[nt][2] = sacc[nt][3] = 0.0f;
            const int cb = nt * 8;
            #pragma unroll
            for (int kk4 = 0; kk4 < 4; kk4++) {
                const int kc = kk4 * 8;
                unsigned bf[2];
                bf[0] = __float_as_uint(ks[(cb + g) * KS_S + kc + tg]);
                bf[1] = __float_as_uint(ks[(cb + g) * KS_S + kc + tg + 4]);
                mma_tf32(sacc[nt], aq[kk4], bf);
            }
            const float2 bA = *reinterpret_cast<const float2*>(
                bmb + (size_t)(rb + g) * NTOK + cb + tg * 2);
            const float2 bB = *reinterpret_cast<const float2*>(
                bmb + (size_t)(rb + 8 + g) * NTOK + cb + tg * 2);
            sacc[nt][0] += bA.x; sacc[nt][1] += bA.y;
            sacc[nt][2] += bB.x; sacc[nt][3] += bB.y;
        }

        // softmax across the 4-lane quad owning each row pair
        float mxA = -1e30f, mxB = -1e30f;
        #pragma unroll
        for (int nt = 0; nt < 18; nt++) {
            mxA = fmaxf(mxA, fmaxf(sacc[nt][0], sacc[nt][1]));
            mxB = fmaxf(mxB, fmaxf(sacc[nt][2], sacc[nt][3]));
        }
        #pragma unroll
        for (int o = 1; o <= 2; o <<= 1) {
            mxA = fmaxf(mxA, __shfl_xor_sync(0xFFFFFFFFu, mxA, o));
            mxB = fmaxf(mxB, __shfl_xor_sync(0xFFFFFFFFu, mxB, o));
        }
        float smA = 0.0f, smB = 0.0f;
        #pragma unroll
        for (int nt = 0; nt < 18; nt++) {
            sacc[nt][0] = __expf(sacc[nt][0] - mxA);
            sacc[nt][1] = __expf(sacc[nt][1] - mxA);
            sacc[nt][2] = __expf(sacc[nt][2] - mxB);
            sacc[nt][3] = __expf(sacc[nt][3] - mxB);
            smA += sacc[nt][0] + sacc[nt][1];
            smB += sacc[nt][2] + sacc[nt][3];
        }
        #pragma unroll
        for (int o = 1; o <= 2; o <<= 1) {
            smA += __shfl_xor_sync(0xFFFFFFFFu, smA, o);
            smB += __shfl_xor_sync(0xFFFFFFFFu, smB, o);
        }
        const float invA = 1.0f / smA;
        const float invB = 1.0f / smB;

        // O = P V, two 72-col chunks through per-warp scratch
        float oacc[4][4];
        #pragma unroll
        for (int nt = 0; nt < 4; nt++)
            oacc[nt][0] = oacc[nt][1] = oacc[nt][2] = oacc[nt][3] = 0.0f;

        #pragma unroll
        for (int ch = 0; ch < 2; ch++) {
            #pragma unroll
            for (int j9 = 0; j9 < 9; j9++) {
                const int nt = ch * 9 + j9;
                const int cc = j9 * 8 + tg * 2;
                *reinterpret_cast<float2*>(&wscr[g * SCR_S + cc]) =
                    make_float2(f2tf32f(sacc[nt][0]), f2tf32f(sacc[nt][1]));
                *reinterpret_cast<float2*>(&wscr[(g + 8) * SCR_S + cc]) =
                    make_float2(f2tf32f(sacc[nt][2]), f2tf32f(sacc[nt][3]));
            }
            __syncwarp();
            #pragma unroll
            for (int kk = 0; kk < 9; kk++) {
                const int kc = kk * 8;
                const int kglob = ch * 72 + kc;
                unsigned ap[4];
                ap[0] = __float_as_uint(wscr[g * SCR_S + kc + tg]);
                ap[1] = __float_as_uint(wscr[(g + 8) * SCR_S + kc + tg]);
                ap[2] = __float_as_uint(wscr[g * SCR_S + kc + tg + 4]);
                ap[3] = __float_as_uint(wscr[(g + 8) * SCR_S + kc + tg + 4]);
                #pragma unroll
                for (int nt = 0; nt < 4; nt++) {
                    unsigned bf[2];
                    bf[0] = __float_as_uint(vs[(kglob + tg)     * VS_S + nt * 8 + g]);
                    bf[1] = __float_as_uint(vs[(kglob + tg + 4) * VS_S + nt * 8 + g]);
                    mma_tf32(oacc[nt], ap, bf);
                }
            }
            __syncwarp();
        }

        #pragma unroll
        for (int nt = 0; nt < 4; nt++) {
            const int c = nt * 8 + tg * 2;
            float* opA = g_ao + ((size_t)win * NTOK + rb + g) * CDIM + head * HD + c;
            float* opB = g_ao + ((size_t)win * NTOK + rb + 8 + g) * CDIM + head * HD + c;
            *reinterpret_cast<float2*>(opA) =
                make_float2(oacc[nt][0] * invA, oacc[nt][1] * invA);
            *reinterpret_cast<float2*>(opB) =
                make_float2(oacc[nt][2] * invB, oacc[nt][3] * invB);
        }
    }
}

// ---------------------------------------------------------------------------
// LayerNorm + residual: x[p] += LN(y[r])*g + b. mode 0: p=r; 1: un-window;
// 2: un-window + un-roll. One warp per row.
// ---------------------------------------------------------------------------
__global__ void ln_add_kernel(const float* __restrict__ y,
                              const float* __restrict__ g,
                              const float* __restrict__ b,
                              int mode) {
    int w = (blockIdx.x * blockDim.x + threadIdx.x) >> 5;
    int lane = threadIdx.x & 31;
    if (w >= MTOK) return;
    size_t p;
    if (mode == 0) {
        p = (size_t)w;
    } else {
        int n = w % NTOK, win = w / NTOK;
        int l = win % NWW, t = win / NWW;
        int tz = t / 8, th = t % 8;
        int z1 = n / 72, h1 = (n % 72) / 12, w1 = n % 12;
        int zr = tz * 2 + z1, hr = th * 6 + h1, wr = l * 12 + w1;
        int z, hh, ww;
        if (mode == 2) { z = (zr + 7) & 7; hh = (hr + 45) % 48; ww = (wr + 186) % 192; }
        else           { z = zr; hh = hr; ww = wr; }
        p = ((size_t)z * 48 + hh) * 192 + ww;
    }
    const float* yr = y + (size_t)w * CDIM;
    float v[6];
    float sum = 0.0f;
    #pragma unroll
    for (int i = 0; i < 6; i++) { v[i] = yr[lane + 32 * i]; sum += v[i]; }
    #pragma unroll
    for (int o = 16; o; o >>= 1) sum += __shfl_xor_sync(0xFFFFFFFFu, sum, o);
    float mu = sum * (1.0f / 192.0f);
    float var = 0.0f;
    #pragma unroll
    for (int i = 0; i < 6; i++) { float d = v[i] - mu; var += d * d; }
    #pragma unroll
    for (int o = 16; o; o >>= 1) var += __shfl_xor_sync(0xFFFFFFFFu, var, o);
    var *= (1.0f / 192.0f);
    float rs = rsqrtf(var + 1e-5f);
    float* xp = g_x + p * CDIM;
    #pragma unroll
    for (int i = 0; i < 6; i++) {
        int c = lane + 32 * i;
        xp[c] += (v[i] - mu) * rs * g[c] + b[c];
    }
}

extern "C" void kernel_launch(void* const* d_in, const int* in_sizes, int n_in,
                              void* d_out, int out_size) {
    const float* x_in       = (const float*)d_in[0];
    const float* qkv_w      = (const float*)d_in[1];
    const float* qkv_b      = (const float*)d_in[2];
    const float* proj_w     = (const float*)d_in[3];
    const float* proj_b     = (const float*)d_in[4];
    const float* bias_table = (const float*)d_in[5];
    const float* n1_g       = (const float*)d_in[6];
    const float* n1_b       = (const float*)d_in[7];
    const float* n2_g       = (const float*)d_in[8];
    const float* n2_b       = (const float*)d_in[9];
    const float* w1         = (const float*)d_in[10];
    const float* b1         = (const float*)d_in[11];
    const float* w2         = (const float*)d_in[12];
    const float* b2         = (const float*)d_in[13];
    // d_in[14..16] = Z,H,W scalars (fixed 8,48,192)

    float *gx, *gqkv, *gao, *gtmp, *gh;
    cudaGetSymbolAddress((void**)&gx,   g_x);
    cudaGetSymbolAddress((void**)&gqkv, g_qkv);
    cudaGetSymbolAddress((void**)&gao,  g_ao);
    cudaGetSymbolAddress((void**)&gtmp, g_tmp);
    cudaGetSymbolAddress((void**)&gh,   g_h);

    const size_t xbytes = (size_t)MTOK * CDIM * sizeof(float);
    cudaMemcpyAsync(gx, x_in, xbytes, cudaMemcpyDeviceToDevice);

    {
        size_t total = (size_t)2 * TWIN * NHEAD * NTOK * NTOK;
        biasmask_kernel<<<(unsigned)((total + 255) / 256), 256>>>(bias_table);
    }

    cudaFuncSetAttribute(mma_gemm_kernel<0,0>, cudaFuncAttributeMaxDynamicSharedMemorySize, GEMM_SMEM);
    cudaFuncSetAttribute(mma_gemm_kernel<1,0>, cudaFuncAttributeMaxDynamicSharedMemorySize, GEMM_SMEM);
    cudaFuncSetAttribute(mma_gemm_kernel<0,1>, cudaFuncAttributeMaxDynamicSharedMemorySize, GEMM_SMEM);
    cudaFuncSetAttribute(attn_mma_kernel, cudaFuncAttributeMaxDynamicSharedMemorySize, ATTN_SMEM);

    for (int L = 0; L < 2; L++) {
        // QKV with fused window gather: (M x 192) @ (192 x 576) + b
        mma_gemm_kernel<0,1><<<dim3(QKVN / 64, MTOK / 128), 256, GEMM_SMEM>>>(
            gx, qkv_w + (size_t)L * CDIM * QKVN, qkv_b + (size_t)L * QKVN,
            gqkv, CDIM, QKVN, L);

        attn_mma_kernel<<<dim3(NWIN, NHEAD), 128, ATTN_SMEM>>>(L);

        // proj: (M x 192) @ (192 x 192) + b
        mma_gemm_kernel<0,0><<<dim3(CDIM / 64, MTOK / 128), 256, GEMM_SMEM>>>(
            gao, proj_w + (size_t)L * CDIM * CDIM, proj_b + (size_t)L * CDIM,
            gtmp, CDIM, CDIM, 0);

        // x += LN(un-window(proj_out))
        ln_add_kernel<<<(MTOK * 32 + 255) / 256, 256>>>(
            gtmp, n1_g + (size_t)L * CDIM, n1_b + (size_t)L * CDIM, L ? 2 : 1);

        // MLP up: gelu((M x 192) @ (192 x 768) + b)
        mma_gemm_kernel<1,0><<<dim3(FFN / 64, MTOK / 128), 256, GEMM_SMEM>>>(
            gx, w1 + (size_t)L * CDIM * FFN, b1 + (size_t)L * FFN,
            gh, CDIM, FFN, 0);

        // MLP down: (M x 768) @ (768 x 192) + b
        mma_gemm_kernel<0,0><<<dim3(CDIM / 64, MTOK / 128), 256, GEMM_SMEM>>>(
            gh, w2 + (size_t)L * FFN * CDIM, b2 + (size_t)L * CDIM,
            gtmp, FFN, CDIM, 0);

        // x += LN(mlp_out)
        ln_add_kernel<<<(MTOK * 32 + 255) / 256, 256>>>(
            gtmp, n2_g + (size_t)L * CDIM, n2_b + (size_t)L * CDIM, 0);
    }

    cudaMemcpyAsync(d_out, gx, xbytes, cudaMemcpyDeviceToDevice);
}

// round 5
// speedup vs baseline: 3.2740x; 1.0959x over previous
#include <cuda_runtime.h>
#include <cuda_bf16.h>
#include <math.h>

#define MTOK   73728
#define CDIM   192
#define NHEAD  6
#define HD     32
#define NTOK   144
#define NWIN   512
#define TWIN   32
#define NWW    16
#define NB     3312
#define QKVN   576
#define FFN    768

__device__ float g_x  [(size_t)MTOK * CDIM];
__device__ float g_qkv[(size_t)MTOK * QKVN];
__device__ float g_ao [(size_t)MTOK * CDIM];
__device__ float g_tmp[(size_t)MTOK * CDIM];
__device__ float g_h  [(size_t)MTOK * FFN];
__device__ float g_bm [(size_t)2 * TWIN * NHEAD * NTOK * NTOK];
// tf32-pre-rounded weights: qkv | proj | w1 | w2  (both layers)
#define WQ_OFF 0
#define WP_OFF 221184
#define W1_OFF 294912
#define W2_OFF 589824
__device__ float g_wt [884736];

// ---------------------------------------------------------------------------
// helpers
// ---------------------------------------------------------------------------
__device__ __forceinline__ unsigned f2tf32(float x) {
    unsigned r;
    asm("cvt.rna.tf32.f32 %0, %1;" : "=r"(r) : "f"(x));
    return r;
}
__device__ __forceinline__ float f2tf32f(float x) { return __uint_as_float(f2tf32(x)); }

__device__ __forceinline__ void mma_tf32(float* d, const unsigned* a, const unsigned* b) {
    asm volatile(
        "mma.sync.aligned.m16n8k8.row.col.f32.tf32.tf32.f32 "
        "{%0,%1,%2,%3}, {%4,%5,%6,%7}, {%8,%9}, {%0,%1,%2,%3};\n"
        : "+f"(d[0]), "+f"(d[1]), "+f"(d[2]), "+f"(d[3])
        : "r"(a[0]), "r"(a[1]), "r"(a[2]), "r"(a[3]),
          "r"(b[0]), "r"(b[1]));
}

__device__ __forceinline__ unsigned smaddr(const void* p) {
    return (unsigned)__cvta_generic_to_shared(p);
}
#define CPA16(dst, src) asm volatile("cp.async.cg.shared.global [%0], [%1], 16;" :: "r"(dst), "l"(src))
#define CPCOMMIT()      asm volatile("cp.async.commit_group;")
#define CPWAIT1()       asm volatile("cp.async.wait_group 1;")

__device__ __forceinline__ float gelu_exact(float v) {
    return 0.5f * v * (1.0f + erff(v * 0.70710678118654752f));
}

// ---------------------------------------------------------------------------
// Pre-round weights to tf32 (cvt.rna is idempotent -> numerics unchanged)
// ---------------------------------------------------------------------------
__global__ void round_weights_kernel(const float* __restrict__ src,
                                     float* __restrict__ dst, int n) {
    int i = blockIdx.x * blockDim.x + threadIdx.x;
    if (i < n) dst[i] = f2tf32f(src[i]);
}

// ---------------------------------------------------------------------------
// Dense (relative-position bias + shift mask)
// ---------------------------------------------------------------------------
__global__ void biasmask_kernel(const float* __restrict__ table) {
    size_t idx = (size_t)blockIdx.x * blockDim.x + threadIdx.x;
    size_t total = (size_t)2 * TWIN * NHEAD * NTOK * NTOK;
    if (idx >= total) return;
    int m = idx % NTOK; size_t r = idx / NTOK;
    int n = r % NTOK;   r /= NTOK;
    int head = r % NHEAD; r /= NHEAD;
    int t = r % TWIN;   int L = (int)(r / TWIN);
    int z1 = n / 72, h1 = (n % 72) / 12, w1 = n % 12;
    int z2 = m / 72, h2 = (m % 72) / 12, w2 = m % 12;
    int pos = 828 * (z1 + 2 * z2) + 23 * (h1 + 6 * h2) + (w1 - w2 + 11);
    float v = table[(((size_t)L * NB + pos) * TWIN + t) * NHEAD + head];
    if (L == 1) {
        int tz = t / 8, th = t % 8;
        int idn = (((tz * 2 + z1) >= 1) ? 2 : 0) + (((th * 6 + h1) >= 3) ? 1 : 0);
        int idm = (((tz * 2 + z2) >= 1) ? 2 : 0) + (((th * 6 + h2) >= 3) ? 1 : 0);
        if (idn != idm) v += -10000.0f;
    }
    g_bm[idx] = v;
}

// ---------------------------------------------------------------------------
// tf32 GEMM, cp.async 2-stage pipeline, BK=32, BM=128, BN=64, 256 threads.
// B comes pre-rounded to tf32 (no cvt on B fragments).
// GATHER=1: A rows remapped (window gather), `rolled` selects shifted map.
// smem: 2 x (As[128][36] + Bs[32][72]) fp32 = 55296 B -> 3 blocks/SM (regs).
// ---------------------------------------------------------------------------
#define ASTG (128 * 36)
#define BSTG (32 * 72)
#define GEMM_SMEM ((2 * ASTG + 2 * BSTG) * 4)

template <int EPI, int GATHER>
__global__ void __launch_bounds__(256, 3)
mma_gemm_kernel(const float* __restrict__ A,
                const float* __restrict__ B,
                const float* __restrict__ bias,
                float* __restrict__ Cm,
                int K, int Nn, int rolled) {
    extern __shared__ float dsm[];
    float* As = dsm;
    float* Bs = dsm + 2 * ASTG;

    const int tid  = threadIdx.x;
    const int lane = tid & 31;
    const int wid  = tid >> 5;
    const int wm   = wid >> 1;
    const int wn   = wid & 1;
    const int g    = lane >> 2;
    const int tg   = lane & 3;
    const int m0   = blockIdx.y * 128;
    const int n0   = blockIdx.x * 64;

    const int arow0 = tid >> 3;        // + 32*i, i<4
    const int akc4  = tid & 7;
    const int brow0 = tid >> 4;        // + 16*i, i<2
    const int bc4   = tid & 15;

    const float* aSrc[4];
    #pragma unroll
    for (int i = 0; i < 4; i++) {
        int r = m0 + arow0 + 32 * i;
        size_t p;
        if (GATHER) {
            int n = r % NTOK, win = r / NTOK;
            int l = win % NWW, t = win / NWW;
            int tz = t / 8, th = t % 8;
            int z1 = n / 72, h1 = (n % 72) / 12, w1 = n % 12;
            int zr = tz * 2 + z1, hr = th * 6 + h1, wr = l * 12 + w1;
            int z, hh, ww;
            if (rolled) { z = (zr + 7) & 7; hh = (hr + 45) % 48; ww = (wr + 186) % 192; }
            else        { z = zr; hh = hr; ww = wr; }
            p = ((size_t)z * 48 + hh) * 192 + ww;
        } else {
            p = (size_t)r;
        }
        aSrc[i] = A + p * K + akc4 * 4;
    }
    const float* bSrc = B + (size_t)brow0 * Nn + n0 + bc4 * 4;

    float acc[2][4][4];
    #pragma unroll
    for (int mt = 0; mt < 2; mt++)
        #pragma unroll
        for (int nt = 0; nt < 4; nt++)
            #pragma unroll
            for (int i = 0; i < 4; i++) acc[mt][nt][i] = 0.0f;

    // prologue: stages 0,1
    #pragma unroll
    for (int s = 0; s < 2; s++) {
        float* as = As + s * ASTG;
        float* bs = Bs + s * BSTG;
        const int k0 = s * 32;
        #pragma unroll
        for (int i = 0; i < 4; i++)
            CPA16(smaddr(as + (arow0 + 32 * i) * 36 + akc4 * 4), aSrc[i] + k0);
        #pragma unroll
        for (int i = 0; i < 2; i++)
            CPA16(smaddr(bs + (brow0 + 16 * i) * 72 + bc4 * 4),
                  bSrc + (size_t)(k0 + 16 * i) * Nn);
        CPCOMMIT();
    }

    const int iters = K >> 5;
    for (int it = 0; it < iters; it++) {
        const int cur = it & 1;
        CPWAIT1();
        __syncthreads();

        const float* as = As + cur * ASTG;
        const float* bs = Bs + cur * BSTG;
        #pragma unroll
        for (int ks = 0; ks < 4; ks++) {
            const int kk = ks * 8;
            unsigned af[2][4], bf[4][2];
            #pragma unroll
            for (int mt = 0; mt < 2; mt++) {
                int rbse = wm * 32 + mt * 16;
                af[mt][0] = f2tf32(as[(rbse + g)     * 36 + kk + tg]);
                af[mt][1] = f2tf32(as[(rbse + 8 + g) * 36 + kk + tg]);
                af[mt][2] = f2tf32(as[(rbse + g)     * 36 + kk + tg + 4]);
                af[mt][3] = f2tf32(as[(rbse + 8 + g) * 36 + kk + tg + 4]);
            }
            #pragma unroll
            for (int nt = 0; nt < 4; nt++) {
                int cb = wn * 32 + nt * 8;
                bf[nt][0] = __float_as_uint(bs[(kk + tg)     * 72 + cb + g]);
                bf[nt][1] = __float_as_uint(bs[(kk + 4 + tg) * 72 + cb + g]);
            }
            #pragma unroll
            for (int mt = 0; mt < 2; mt++)
                #pragma unroll
                for (int nt = 0; nt < 4; nt++)
                    mma_tf32(acc[mt][nt], af[mt], bf[nt]);
        }
        __syncthreads();   // all warps done with slot `cur` before refill

        const int k0n = (it + 2) << 5;
        if (k0n < K) {
            float* asw = As + cur * ASTG;
            float* bsw = Bs + cur * BSTG;
            #pragma unroll
            for (int i = 0; i < 4; i++)
                CPA16(smaddr(asw + (arow0 + 32 * i) * 36 + akc4 * 4), aSrc[i] + k0n);
            #pragma unroll
            for (int i = 0; i < 2; i++)
                CPA16(smaddr(bsw + (brow0 + 16 * i) * 72 + bc4 * 4),
                      bSrc + (size_t)(k0n + 16 * i) * Nn);
        }
        CPCOMMIT();
    }

    #pragma unroll
    for (int mt = 0; mt < 2; mt++) {
        int r0 = m0 + wm * 32 + mt * 16 + g;
        #pragma unroll
        for (int nt = 0; nt < 4; nt++) {
            int c = n0 + wn * 32 + nt * 8 + tg * 2;
            float b0 = bias[c], b1 = bias[c + 1];
            float v0 = acc[mt][nt][0] + b0;
            float v1 = acc[mt][nt][1] + b1;
            float v2 = acc[mt][nt][2] + b0;
            float v3 = acc[mt][nt][3] + b1;
            if (EPI == 1) {
                v0 = gelu_exact(v0); v1 = gelu_exact(v1);
                v2 = gelu_exact(v2); v3 = gelu_exact(v3);
            }
            *reinterpret_cast<float2*>(Cm + (size_t)r0 * Nn + c)       = make_float2(v0, v1);
            *reinterpret_cast<float2*>(Cm + (size_t)(r0 + 8) * Nn + c) = make_float2(v2, v3);
        }
    }
}

// ---------------------------------------------------------------------------
// Tensor-core window attention (conflict-free pads; Q fragments from gmem).
// ---------------------------------------------------------------------------
#define KS_S  36
#define VS_S  40
#define SCR_S 76
#define ATTN_SMEM ((NTOK * KS_S + NTOK * VS_S + 4 * 16 * SCR_S) * 4)

__global__ void __launch_bounds__(128, 3) attn_mma_kernel(int L) {
    const int win  = blockIdx.x;
    const int head = blockIdx.y;
    const int t    = win >> 4;
    extern __shared__ float sm[];
    float* ks  = sm;                        // [144][36]
    float* vs  = ks + NTOK * KS_S;          // [144][40]
    float* scr = vs + NTOK * VS_S;          // 4 x [16][76]

    const int tid  = threadIdx.x;
    const int lane = tid & 31;
    const int wid  = tid >> 5;
    const int g    = lane >> 2;
    const int tg   = lane & 3;

    const float* base = g_qkv + (size_t)win * NTOK * QKVN;
    const int hc4 = head * 8;
    for (int idx = tid; idx < NTOK * 8; idx += 128) {
        int row = idx >> 3, j = idx & 7;
        const float4* rp = reinterpret_cast<const float4*>(base + (size_t)row * QKVN);
        float4 k4 = rp[48 + hc4 + j];
        float4 v4 = rp[96 + hc4 + j];
        *reinterpret_cast<float4*>(&ks[row * KS_S + j * 4]) =
            make_float4(f2tf32f(k4.x), f2tf32f(k4.y), f2tf32f(k4.z), f2tf32f(k4.w));
        *reinterpret_cast<float4*>(&vs[row * VS_S + j * 4]) =
            make_float4(f2tf32f(v4.x), f2tf32f(v4.y), f2tf32f(v4.z), f2tf32f(v4.w));
    }
    __syncthreads();

    const float* bmb = g_bm + (((size_t)L * TWIN + t) * NHEAD + head) * NTOK * NTOK;
    float* wscr = scr + wid * 16 * SCR_S;
    const float sc = 0.17677669529663687f;

    for (int mt = wid; mt < 9; mt += 4) {
        const int rb = mt * 16;

        const float* qA = g_qkv + (size_t)(win * NTOK + rb + g) * QKVN + head * HD;
        const float* qB = g_qkv + (size_t)(win * NTOK + rb + 8 + g) * QKVN + head * HD;
        unsigned aq[4][4];
        #pragma unroll
        for (int kk4 = 0; kk4 < 4; kk4++) {
            const int kc = kk4 * 8;
            aq[kk4][0] = f2tf32(qA[kc + tg] * sc);
            aq[kk4][1] = f2tf32(qB[kc + tg] * sc);
            aq[kk4][2] = f2tf32(qA[kc + tg + 4] * sc);
            aq[kk4][3] = f2tf32(qB[kc + tg + 4] * sc);
        }

        float sacc[18][4];
        #pragma unroll
        for (int nt = 0; nt < 18; nt++) {
            sacc[nt][0] = sacc[nt][1] = sacc[nt][2] = sacc[nt][3] = 0.0f;
            const int cb = nt * 8;
            #pragma unroll
            for (int kk4 = 0; kk4 < 4; kk4++) {
                const int kc = kk4 * 8;
                unsigned bf[2];
                bf[0] = __float_as_uint(ks[(cb + g) * KS_S + kc + tg]);
                bf[1] = __float_as_uint(ks[(cb + g) * KS_S + kc + tg + 4]);
                mma_tf32(sacc[nt], aq[kk4], bf);
            }
            const float2 bA = *reinterpret_cast<const float2*>(
                bmb + (size_t)(rb + g) * NTOK + cb + tg * 2);
            const float2 bB = *reinterpret_cast<const float2*>(
                bmb + (size_t)(rb + 8 + g) * NTOK + cb + tg * 2);
            sacc[nt][0] += bA.x; sacc[nt][1] += bA.y;
            sacc[nt][2] += bB.x; sacc[nt][3] += bB.y;
        }

        float mxA = -1e30f, mxB = -1e30f;
        #pragma unroll
        for (int nt = 0; nt < 18; nt++) {
            mxA = fmaxf(mxA, fmaxf(sacc[nt][0], sacc[nt][1]));
            mxB = fmaxf(mxB, fmaxf(sacc[nt][2], sacc[nt][3]));
        }
        #pragma unroll
        for (int o = 1; o <= 2; o <<= 1) {
            mxA = fmaxf(mxA, __shfl_xor_sync(0xFFFFFFFFu, mxA, o));
            mxB = fmaxf(mxB, __shfl_xor_sync(0xFFFFFFFFu, mxB, o));
        }
        float smA = 0.0f, smB = 0.0f;
        #pragma unroll
        for (int nt = 0; nt < 18; nt++) {
            sacc[nt][0] = __expf(sacc[nt][0] - mxA);
            sacc[nt][1] = __expf(sacc[nt][1] - mxA);
            sacc[nt][2] = __expf(sacc[nt][2] - mxB);
            sacc[nt][3] = __expf(sacc[nt][3] - mxB);
            smA += sacc[nt][0] + sacc[nt][1];
            smB += sacc[nt][2] + sacc[nt][3];
        }
        #pragma unroll
        for (int o = 1; o <= 2; o <<= 1) {
            smA += __shfl_xor_sync(0xFFFFFFFFu, smA, o);
            smB += __shfl_xor_sync(0xFFFFFFFFu, smB, o);
        }
        const float invA = 1.0f / smA;
        const float invB = 1.0f / smB;

        float oacc[4][4];
        #pragma unroll
        for (int nt = 0; nt < 4; nt++)
            oacc[nt][0] = oacc[nt][1] = oacc[nt][2] = oacc[nt][3] = 0.0f;

        #pragma unroll
        for (int ch = 0; ch < 2; ch++) {
            #pragma unroll
            for (int j9 = 0; j9 < 9; j9++) {
                const int nt = ch * 9 + j9;
                const int cc = j9 * 8 + tg * 2;
                *reinterpret_cast<float2*>(&wscr[g * SCR_S + cc]) =
                    make_float2(f2tf32f(sacc[nt][0]), f2tf32f(sacc[nt][1]));
                *reinterpret_cast<float2*>(&wscr[(g + 8) * SCR_S + cc]) =
                    make_float2(f2tf32f(sacc[nt][2]), f2tf32f(sacc[nt][3]));
            }
            __syncwarp();
            #pragma unroll
            for (int kk = 0; kk < 9; kk++) {
                const int kc = kk * 8;
                const int kglob = ch * 72 + kc;
                unsigned ap[4];
                ap[0] = __float_as_uint(wscr[g * SCR_S + kc + tg]);
                ap[1] = __float_as_uint(wscr[(g + 8) * SCR_S + kc + tg]);
                ap[2] = __float_as_uint(wscr[g * SCR_S + kc + tg + 4]);
                ap[3] = __float_as_uint(wscr[(g + 8) * SCR_S + kc + tg + 4]);
                #pragma unroll
                for (int nt = 0; nt < 4; nt++) {
                    unsigned bf[2];
                    bf[0] = __float_as_uint(vs[(kglob + tg)     * VS_S + nt * 8 + g]);
                    bf[1] = __float_as_uint(vs[(kglob + tg + 4) * VS_S + nt * 8 + g]);
                    mma_tf32(oacc[nt], ap, bf);
                }
            }
            __syncwarp();
        }

        #pragma unroll
        for (int nt = 0; nt < 4; nt++) {
            const int c = nt * 8 + tg * 2;
            float* opA = g_ao + ((size_t)win * NTOK + rb + g) * CDIM + head * HD + c;
            float* opB = g_ao + ((size_t)win * NTOK + rb + 8 + g) * CDIM + head * HD + c;
            *reinterpret_cast<float2*>(opA) =
                make_float2(oacc[nt][0] * invA, oacc[nt][1] * invA);
            *reinterpret_cast<float2*>(opB) =
                make_float2(oacc[nt][2] * invB, oacc[nt][3] * invB);
        }
    }
}

// ---------------------------------------------------------------------------
// LayerNorm + residual: xout[p] = xin[p] + LN(y[r])*g + b.
// mode 0: p=r; 1: un-window; 2: un-window + un-roll.  One warp per row.
// ---------------------------------------------------------------------------
__global__ void ln_add_kernel(const float* __restrict__ y,
                              const float* __restrict__ g,
                              const float* __restrict__ b,
                              const float* __restrict__ xin,
                              float* __restrict__ xout,
                              int mode) {
    int w = (blockIdx.x * blockDim.x + threadIdx.x) >> 5;
    int lane = threadIdx.x & 31;
    if (w >= MTOK) return;
    size_t p;
    if (mode == 0) {
        p = (size_t)w;
    } else {
        int n = w % NTOK, win = w / NTOK;
        int l = win % NWW, t = win / NWW;
        int tz = t / 8, th = t % 8;
        int z1 = n / 72, h1 = (n % 72) / 12, w1 = n % 12;
        int zr = tz * 2 + z1, hr = th * 6 + h1, wr = l * 12 + w1;
        int z, hh, ww;
        if (mode == 2) { z = (zr + 7) & 7; hh = (hr + 45) % 48; ww = (wr + 186) % 192; }
        else           { z = zr; hh = hr; ww = wr; }
        p = ((size_t)z * 48 + hh) * 192 + ww;
    }
    const float* yr = y + (size_t)w * CDIM;
    float v[6];
    float sum = 0.0f;
    #pragma unroll
    for (int i = 0; i < 6; i++) { v[i] = yr[lane + 32 * i]; sum += v[i]; }
    #pragma unroll
    for (int o = 16; o; o >>= 1) sum += __shfl_xor_sync(0xFFFFFFFFu, sum, o);
    float mu = sum * (1.0f / 192.0f);
    float var = 0.0f;
    #pragma unroll
    for (int i = 0; i < 6; i++) { float d = v[i] - mu; var += d * d; }
    #pragma unroll
    for (int o = 16; o; o >>= 1) var += __shfl_xor_sync(0xFFFFFFFFu, var, o);
    var *= (1.0f / 192.0f);
    float rs = rsqrtf(var + 1e-5f);
    const float* xi = xin + p * CDIM;
    float* xo = xout + p * CDIM;
    #pragma unroll
    for (int i = 0; i < 6; i++) {
        int c = lane + 32 * i;
        xo[c] = xi[c] + (v[i] - mu) * rs * g[c] + b[c];
    }
}

extern "C" void kernel_launch(void* const* d_in, const int* in_sizes, int n_in,
                              void* d_out, int out_size) {
    const float* x_in       = (const float*)d_in[0];
    const float* qkv_w      = (const float*)d_in[1];
    const float* qkv_b      = (const float*)d_in[2];
    const float* proj_w     = (const float*)d_in[3];
    const float* proj_b     = (const float*)d_in[4];
    const float* bias_table = (const float*)d_in[5];
    const float* n1_g       = (const float*)d_in[6];
    const float* n1_b       = (const float*)d_in[7];
    const float* n2_g       = (const float*)d_in[8];
    const float* n2_b       = (const float*)d_in[9];
    const float* w1         = (const float*)d_in[10];
    const float* b1         = (const float*)d_in[11];
    const float* w2         = (const float*)d_in[12];
    const float* b2         = (const float*)d_in[13];
    // d_in[14..16] = Z,H,W scalars (fixed 8,48,192)

    float *gx, *gqkv, *gao, *gtmp, *gh, *gwt;
    cudaGetSymbolAddress((void**)&gx,   g_x);
    cudaGetSymbolAddress((void**)&gqkv, g_qkv);
    cudaGetSymbolAddress((void**)&gao,  g_ao);
    cudaGetSymbolAddress((void**)&gtmp, g_tmp);
    cudaGetSymbolAddress((void**)&gh,   g_h);
    cudaGetSymbolAddress((void**)&gwt,  g_wt);

    // pre-round all weights to tf32 (idempotent under later cvt)
    round_weights_kernel<<<(221184 + 255) / 256, 256>>>(qkv_w,  gwt + WQ_OFF, 221184);
    round_weights_kernel<<<( 73728 + 255) / 256, 256>>>(proj_w, gwt + WP_OFF,  73728);
    round_weights_kernel<<<(294912 + 255) / 256, 256>>>(w1,     gwt + W1_OFF, 294912);
    round_weights_kernel<<<(294912 + 255) / 256, 256>>>(w2,     gwt + W2_OFF, 294912);

    {
        size_t total = (size_t)2 * TWIN * NHEAD * NTOK * NTOK;
        biasmask_kernel<<<(unsigned)((total + 255) / 256), 256>>>(bias_table);
    }

    cudaFuncSetAttribute(mma_gemm_kernel<0,0>, cudaFuncAttributeMaxDynamicSharedMemorySize, GEMM_SMEM);
    cudaFuncSetAttribute(mma_gemm_kernel<1,0>, cudaFuncAttributeMaxDynamicSharedMemorySize, GEMM_SMEM);
    cudaFuncSetAttribute(mma_gemm_kernel<0,1>, cudaFuncAttributeMaxDynamicSharedMemorySize, GEMM_SMEM);
    cudaFuncSetAttribute(attn_mma_kernel, cudaFuncAttributeMaxDynamicSharedMemorySize, ATTN_SMEM);

    for (int L = 0; L < 2; L++) {
        const float* xsrc = (L == 0) ? x_in : gx;

        // QKV with fused window gather: (M x 192) @ (192 x 576) + b
        mma_gemm_kernel<0,1><<<dim3(QKVN / 64, MTOK / 128), 256, GEMM_SMEM>>>(
            xsrc, gwt + WQ_OFF + (size_t)L * CDIM * QKVN, qkv_b + (size_t)L * QKVN,
            gqkv, CDIM, QKVN, L);

        attn_mma_kernel<<<dim3(NWIN, NHEAD), 128, ATTN_SMEM>>>(L);

        // proj: (M x 192) @ (192 x 192) + b
        mma_gemm_kernel<0,0><<<dim3(CDIM / 64, MTOK / 128), 256, GEMM_SMEM>>>(
            gao, gwt + WP_OFF + (size_t)L * CDIM * CDIM, proj_b + (size_t)L * CDIM,
            gtmp, CDIM, CDIM, 0);

        // x = xsrc + LN(un-window(proj_out))
        ln_add_kernel<<<(MTOK * 32 + 255) / 256, 256>>>(
            gtmp, n1_g + (size_t)L * CDIM, n1_b + (size_t)L * CDIM,
            xsrc, gx, L ? 2 : 1);

        // MLP up: gelu((M x 192) @ (192 x 768) + b)
        mma_gemm_kernel<1,0><<<dim3(FFN / 64, MTOK / 128), 256, GEMM_SMEM>>>(
            gx, gwt + W1_OFF + (size_t)L * CDIM * FFN, b1 + (size_t)L * FFN,
            gh, CDIM, FFN, 0);

        // MLP down: (M x 768) @ (768 x 192) + b
        mma_gemm_kernel<0,0><<<dim3(CDIM / 64, MTOK / 128), 256, GEMM_SMEM>>>(
            gh, gwt + W2_OFF + (size_t)L * FFN * CDIM, b2 + (size_t)L * CDIM,
            gtmp, FFN, CDIM, 0);

        // x = x + LN(mlp_out); final layer writes straight to d_out
        float* xo = (L == 1) ? (float*)d_out : gx;
        ln_add_kernel<<<(MTOK * 32 + 255) / 256, 256>>>(
            gtmp, n2_g + (size_t)L * CDIM, n2_b + (size_t)L * CDIM,
            gx, xo, 0);
    }
}